// round 1
// baseline (speedup 1.0000x reference)
#include <cuda_runtime.h>
#include <cstdint>

// ---------------- problem constants ----------------
#define NUM_Q   3000
#define EMB     256
#define HID     256
#define BATCH   32
#define SEQ     500
#define MTOT    (BATCH * SEQ)        // 16000
#define KX      (2 * NUM_Q)          // 6000

// ---------------- scratch (static device globals; no runtime alloc) ----------------
__device__ float g_quesP[KX * 512];                 // packed [6000][512] = ques_h | ques_d
__device__ float g_xe[MTOT * 512];                  // [16000][512]  cols 0:256 = x_h, 256:512 = x_d
__device__ float g_xproj[2L * MTOT * 768];          // [2][16000][768]
__device__ float g_out[2L * MTOT * 256 + 4096];     // [2][16000][256] (+pad for K=512 overread)
__device__ float g_attn[BATCH * SEQ * 512];         // [32][500][512] (cols 500..511 zeroed)
__device__ float g_ens[MTOT * 512];                 // [16000][512]
__device__ float g_colsum[BATCH * 256];             // [32][256]

// ---------------- small helpers ----------------
__device__ __forceinline__ unsigned long long dupf2(float x) {
    unsigned long long r;
    asm("mov.b64 %0, {%1, %1};" : "=l"(r) : "f"(x));
    return r;
}
__device__ __forceinline__ float2 unpackf2(unsigned long long v) {
    float2 f;
    asm("mov.b64 {%0, %1}, %2;" : "=f"(f.x), "=f"(f.y) : "l"(v));
    return f;
}
#define FMA2(d, a, b) asm("fma.rn.f32x2 %0, %1, %2, %0;" : "+l"(d) : "l"(a), "l"(b))

__device__ __forceinline__ unsigned smem_u32(const void* p) {
    unsigned r;
    asm("{ .reg .u64 t; cvta.to.shared.u64 t, %1; cvt.u32.u64 %0, t; }" : "=r"(r) : "l"(p));
    return r;
}
#define CLUSTER_SYNC_() do { \
    asm volatile("barrier.cluster.arrive.aligned;" ::: "memory"); \
    asm volatile("barrier.cluster.wait.aligned;"   ::: "memory"); } while (0)

// ---------------- pack question tables ----------------
__global__ void packq_kernel(const float* __restrict__ qh, const float* __restrict__ qd,
                             float* __restrict__ dst) {
    int idx = blockIdx.x * 256 + threadIdx.x;           // over 6000*512
    int k = idx >> 9, c = idx & 511;
    float v = (c < 256) ? qh[k * 256 + c] : qd[k * 256 + (c - 256)];
    dst[idx] = v;
}

// ---------------- generic tiled fp32 GEMM, f32x2-packed ----------------
// C[m][n] = sum_k A[m][k] * B(k,n) (+bias[n])   BT=false: B row-major [K][N]
//                                               BT=true : B row-major [N][K]
// EPI==1: C[m][n] = colsum[z*256+n] - acc  (used for (1-attn)@out_h)
#define BM 128
#define BN 64
#define BKT 16

template <bool BT, int EPI>
__global__ __launch_bounds__(256)
void gemm_kernel(const float* __restrict__ A, const float* __restrict__ B,
                 float* __restrict__ C, const float* __restrict__ bias,
                 const float* __restrict__ colsum,
                 int M, int N, int K, int lda, int ldb, int ldc,
                 long sA, long sB, long sC) {
    __shared__ __align__(16) float As[BKT][BM + 4];   // stride 132 (16B-mult)
    __shared__ __align__(16) float Bs[BKT][BN + 4];   // stride 68  (16B-mult)

    const int z = blockIdx.z;
    A += (long)z * sA;  B += (long)z * sB;  C += (long)z * sC;

    const int row0 = blockIdx.y * BM;
    const int col0 = blockIdx.x * BN;
    const int tid = threadIdx.x;
    const int tx = tid & 15;        // 16 cols of threads (TN=4)
    const int ty = tid >> 4;        // 16 rows of threads (TM=8)

    unsigned long long acc2[4][4] = {};   // [row-pair][n] ; each = 2 fp32

    for (int k0 = 0; k0 < K; k0 += BKT) {
        // load A tile 128x16 (2 passes of float4)
        #pragma unroll
        for (int p = 0; p < 2; ++p) {
            int idx = tid + p * 256;          // 0..511
            int r = idx >> 2;
            int kq = (idx & 3) << 2;
            int gr = row0 + r;
            float4 v = make_float4(0.f, 0.f, 0.f, 0.f);
            if (gr < M) v = *(const float4*)(A + (long)gr * lda + k0 + kq);
            As[kq + 0][r] = v.x; As[kq + 1][r] = v.y;
            As[kq + 2][r] = v.z; As[kq + 3][r] = v.w;
        }
        // load B tile 16x64
        if (!BT) {
            int kk = tid >> 4;
            int nq = (tid & 15) << 2;
            int gn = col0 + nq;
            float4 v = make_float4(0.f, 0.f, 0.f, 0.f);
            if (gn < N) v = *(const float4*)(B + (long)(k0 + kk) * ldb + gn);
            *(float4*)&Bs[kk][nq] = v;
        } else {
            int r = tid >> 2;                 // n-row within tile
            int kq = (tid & 3) << 2;
            int gn = col0 + r;
            float4 v = make_float4(0.f, 0.f, 0.f, 0.f);
            if (gn < N) v = *(const float4*)(B + (long)gn * ldb + k0 + kq);
            Bs[kq + 0][r] = v.x; Bs[kq + 1][r] = v.y;
            Bs[kq + 2][r] = v.z; Bs[kq + 3][r] = v.w;
        }
        __syncthreads();

        #pragma unroll
        for (int kk = 0; kk < BKT; ++kk) {
            const ulonglong2 aA = *(const ulonglong2*)&As[kk][ty * 8];
            const ulonglong2 aB = *(const ulonglong2*)&As[kk][ty * 8 + 4];
            const float4 b4 = *(const float4*)&Bs[kk][tx * 4];
            unsigned long long bd0 = dupf2(b4.x), bd1 = dupf2(b4.y);
            unsigned long long bd2 = dupf2(b4.z), bd3 = dupf2(b4.w);
            FMA2(acc2[0][0], aA.x, bd0); FMA2(acc2[0][1], aA.x, bd1);
            FMA2(acc2[0][2], aA.x, bd2); FMA2(acc2[0][3], aA.x, bd3);
            FMA2(acc2[1][0], aA.y, bd0); FMA2(acc2[1][1], aA.y, bd1);
            FMA2(acc2[1][2], aA.y, bd2); FMA2(acc2[1][3], aA.y, bd3);
            FMA2(acc2[2][0], aB.x, bd0); FMA2(acc2[2][1], aB.x, bd1);
            FMA2(acc2[2][2], aB.x, bd2); FMA2(acc2[2][3], aB.x, bd3);
            FMA2(acc2[3][0], aB.y, bd0); FMA2(acc2[3][1], aB.y, bd1);
            FMA2(acc2[3][2], aB.y, bd2); FMA2(acc2[3][3], aB.y, bd3);
        }
        __syncthreads();
    }

    #pragma unroll
    for (int pi = 0; pi < 4; ++pi) {
        #pragma unroll
        for (int j = 0; j < 4; ++j) {
            int gn = col0 + tx * 4 + j;
            if (gn >= N) continue;
            float2 pv = unpackf2(acc2[pi][j]);
            float v0 = pv.x, v1 = pv.y;
            if (EPI == 1) {
                float cs = colsum[z * 256 + gn];
                v0 = cs - v0; v1 = cs - v1;
            } else if (bias) {
                float bv = bias[gn];
                v0 += bv; v1 += bv;
            }
            int r0 = row0 + ty * 8 + pi * 2;
            if (r0 < M)     C[(long)r0 * ldc + gn] = v0;
            if (r0 + 1 < M) C[(long)(r0 + 1) * ldc + gn] = v1;
        }
    }
}

// ---------------- GRU recurrence: cluster-of-8 persistent scan ----------------
// grid (8 ranks, 8 batch-groups, 2 grus), block 128. Each CTA owns 32 hidden
// units (96 W_hh rows: r/z/n gates), holds full h[4 batches][256] double-buffered,
// broadcasts its h_new slice to all 8 peers via DSMEM each step.
#define GRU_SMEM_FLOATS (96 * 260 + 96 + 2 * 1024 + 96 * 4)
#define GRU_SMEM_BYTES  (GRU_SMEM_FLOATS * 4)

__global__ void __cluster_dims__(8, 1, 1) __launch_bounds__(128, 1)
gru_kernel(const float* __restrict__ xproj,
           const float* __restrict__ whh1, const float* __restrict__ whh2,
           const float* __restrict__ bhh1, const float* __restrict__ bhh2,
           float* __restrict__ out) {
    extern __shared__ __align__(16) float sm[];
    float* Wm     = sm;                   // [96][260] padded rows
    float* bias_s = sm + 96 * 260;        // [96]
    float* h_s    = bias_s + 96;          // [2][4][256]
    float* gh_s   = h_s + 2048;           // [96][4]

    const int rank = blockIdx.x;
    const int bg   = blockIdx.y;
    const int gru  = blockIdx.z;
    const int tid  = threadIdx.x;

    const float* whh = gru ? whh2 : whh1;
    const float* bhh = gru ? bhh2 : bhh1;

    // load W slice: local row lr -> global row (lr/32)*256 + rank*32 + lr%32
    for (int idx = tid; idx < 96 * 256; idx += 128) {
        int lr = idx >> 8, k = idx & 255;
        int grow = ((lr >> 5) << 8) + (rank << 5) + (lr & 31);
        Wm[lr * 260 + k] = whh[grow * 256 + k];
    }
    if (tid < 96)
        bias_s[tid] = bhh[((tid >> 5) << 8) + (rank << 5) + (tid & 31)];
    for (int i = tid; i < 2048; i += 128) h_s[i] = 0.f;
    __syncthreads();
    CLUSTER_SYNC_();   // all peers' h buffers zeroed before any DSMEM writes

    const int b  = tid >> 5;            // phase-2 batch (0..3)
    const int jj = tid & 31;
    const int jg = (rank << 5) + jj;    // global hidden index
    const long mbase = (long)gru * MTOT + (long)bg * 4 * SEQ;
    const float* xp0 = xproj + mbase * 768;
    float* outp = out + mbase * 256;

    for (int t = 0; t < SEQ; ++t) {
        float* hc = h_s + ((t & 1) << 10);
        float* hn = h_s + (((t & 1) ^ 1) << 10);

        // prefetch this step's input projections (hidden behind phase 1)
        const float* xp = xp0 + ((long)b * SEQ + t) * 768;
        float xr = xp[jg], xz = xp[jg + 256], xn = xp[jg + 512];

        // phase 1: gh[row][b] = W[row] . h[b]  (96 rows x 4 batches)
        if (tid < 96) {
            const float* wrow = Wm + tid * 260;
            unsigned long long acc[4][2] = {};
            #pragma unroll 16
            for (int k = 0; k < 256; k += 4) {
                ulonglong2 w2 = *(const ulonglong2*)(wrow + k);
                #pragma unroll
                for (int bb = 0; bb < 4; ++bb) {
                    ulonglong2 h2 = *(const ulonglong2*)(hc + (bb << 8) + k);
                    FMA2(acc[bb][0], w2.x, h2.x);
                    FMA2(acc[bb][1], w2.y, h2.y);
                }
            }
            #pragma unroll
            for (int bb = 0; bb < 4; ++bb) {
                float2 p = unpackf2(acc[bb][0]);
                float2 q = unpackf2(acc[bb][1]);
                gh_s[tid * 4 + bb] = p.x + p.y + q.x + q.y + bias_s[tid];
            }
        }
        __syncthreads();

        // phase 2: gates + state update for (b, jj)
        {
            float ghr = gh_s[jj * 4 + b];
            float ghz = gh_s[(32 + jj) * 4 + b];
            float ghn = gh_s[(64 + jj) * 4 + b];
            float r = 1.f / (1.f + __expf(-(xr + ghr)));
            float z = 1.f / (1.f + __expf(-(xz + ghz)));
            float n = tanhf(xn + r * ghn);
            float hnew = (1.f - z) * n + z * hc[(b << 8) + jg];
            outp[((long)b * SEQ + t) * 256 + jg] = hnew;

            unsigned laddr = smem_u32(hn + (b << 8) + jg);
            unsigned hbits = __float_as_uint(hnew);
            #pragma unroll
            for (int rd = 0; rd < 8; ++rd) {
                unsigned raddr;
                asm volatile("mapa.shared::cluster.u32 %0, %1, %2;"
                             : "=r"(raddr) : "r"(laddr), "r"(rd));
                asm volatile("st.shared::cluster.b32 [%0], %1;"
                             :: "r"(raddr), "r"(hbits) : "memory");
            }
        }
        CLUSTER_SYNC_();   // h_new visible everywhere; also block-level barrier
    }
}

// ---------------- softmax over rows of 500 (ld 512), zero-pads cols 500..511 ----------------
__global__ void softmax_kernel(float* __restrict__ attn) {
    __shared__ float red[8];
    float* p = attn + (long)blockIdx.x * 512;
    int tid = threadIdx.x;
    float v1 = (tid < 500)       ? p[tid]       : -1e30f;
    float v2 = (tid + 256 < 500) ? p[tid + 256] : -1e30f;

    float m = fmaxf(v1, v2);
    #pragma unroll
    for (int o = 16; o; o >>= 1) m = fmaxf(m, __shfl_xor_sync(~0u, m, o));
    if ((tid & 31) == 0) red[tid >> 5] = m;
    __syncthreads();
    if (tid == 0) {
        float mm = red[0];
        #pragma unroll
        for (int i = 1; i < 8; ++i) mm = fmaxf(mm, red[i]);
        red[0] = mm;
    }
    __syncthreads();
    m = red[0];
    __syncthreads();

    float e1 = (tid < 500)       ? __expf(v1 - m) : 0.f;
    float e2 = (tid + 256 < 500) ? __expf(v2 - m) : 0.f;
    float s = e1 + e2;
    #pragma unroll
    for (int o = 16; o; o >>= 1) s += __shfl_xor_sync(~0u, s, o);
    if ((tid & 31) == 0) red[tid >> 5] = s;
    __syncthreads();
    if (tid == 0) {
        float ss = 0.f;
        #pragma unroll
        for (int i = 0; i < 8; ++i) ss += red[i];
        red[0] = ss;
    }
    __syncthreads();
    float inv = 1.f / red[0];

    if (tid < 500) p[tid] = e1 * inv;
    p[tid + 256] = e2 * inv;   // writes exact 0 to cols 500..511
}

// ---------------- column sum of out_h per batch: colsum[b][j] = sum_t out_h[b,t,j] ----------------
__global__ void colsum_kernel(const float* __restrict__ outh, float* __restrict__ cs) {
    int b = blockIdx.x, j = threadIdx.x;
    const float* p = outh + (long)b * SEQ * 256 + j;
    float s = 0.f;
    for (int t = 0; t < SEQ; ++t) s += p[(long)t * 256];
    cs[b * 256 + j] = s;
}

// ---------------- host orchestration ----------------
static void launch_gemm_nn(const float* A, const float* B, float* C, const float* bias,
                           int M, int N, int K, int lda, int ldb, int ldc,
                           long sA, long sB, long sC, int batch) {
    dim3 grid((N + BN - 1) / BN, (M + BM - 1) / BM, batch);
    gemm_kernel<false, 0><<<grid, 256>>>(A, B, C, bias, nullptr, M, N, K, lda, ldb, ldc, sA, sB, sC);
}
static void launch_gemm_nt(const float* A, const float* B, float* C, const float* bias,
                           int M, int N, int K, int lda, int ldb, int ldc,
                           long sA, long sB, long sC, int batch) {
    dim3 grid((N + BN - 1) / BN, (M + BM - 1) / BM, batch);
    gemm_kernel<true, 0><<<grid, 256>>>(A, B, C, bias, nullptr, M, N, K, lda, ldb, ldc, sA, sB, sC);
}
static void launch_gemm_nn_inv(const float* A, const float* B, float* C, const float* colsum,
                               int M, int N, int K, int lda, int ldb, int ldc,
                               long sA, long sB, long sC, int batch) {
    dim3 grid((N + BN - 1) / BN, (M + BM - 1) / BM, batch);
    gemm_kernel<false, 1><<<grid, 256>>>(A, B, C, nullptr, colsum, M, N, K, lda, ldb, ldc, sA, sB, sC);
}

extern "C" void kernel_launch(void* const* d_in, const int* in_sizes, int n_in,
                              void* d_out, int out_size) {
    const float* x      = (const float*)d_in[0];
    const float* qh     = (const float*)d_in[1];
    const float* qd     = (const float*)d_in[2];
    const float* g1wih  = (const float*)d_in[3];
    const float* g1whh  = (const float*)d_in[4];
    const float* g1bih  = (const float*)d_in[5];
    const float* g1bhh  = (const float*)d_in[6];
    const float* g2wih  = (const float*)d_in[7];
    const float* g2whh  = (const float*)d_in[8];
    const float* g2bih  = (const float*)d_in[9];
    const float* g2bhh  = (const float*)d_in[10];
    const float* fccw   = (const float*)d_in[11];
    const float* fccb   = (const float*)d_in[12];
    const float* fctw   = (const float*)d_in[13];
    const float* fctb   = (const float*)d_in[14];
    const float* fcew   = (const float*)d_in[15];
    const float* fceb   = (const float*)d_in[16];
    float* out = (float*)d_out;

    float *quesP, *xe, *xproj, *gout, *attn, *ens, *colsum;
    cudaGetSymbolAddress((void**)&quesP,  g_quesP);
    cudaGetSymbolAddress((void**)&xe,     g_xe);
    cudaGetSymbolAddress((void**)&xproj,  g_xproj);
    cudaGetSymbolAddress((void**)&gout,   g_out);
    cudaGetSymbolAddress((void**)&attn,   g_attn);
    cudaGetSymbolAddress((void**)&ens,    g_ens);
    cudaGetSymbolAddress((void**)&colsum, g_colsum);

    // 1. pack question tables: [6000][512]
    packq_kernel<<<(KX * 512) / 256, 256>>>(qh, qd, quesP);

    // 2. embeddings: g_xe[16000][512] = x @ quesP   (reads x once)
    launch_gemm_nn(x, quesP, xe, nullptr, MTOT, 512, KX, KX, 512, 512, 0, 0, 0, 1);

    // 3. input projections: x_proj = x_emb @ w_ih^T + b_ih   -> [2][16000][768]
    launch_gemm_nt(xe,       g1wih, xproj,                      g1bih, MTOT, 768, 256, 512, 256, 768, 0, 0, 0, 1);
    launch_gemm_nt(xe + 256, g2wih, xproj + (long)MTOT * 768,   g2bih, MTOT, 768, 256, 512, 256, 768, 0, 0, 0, 1);

    // 4. GRU scans (both GRUs, all batches) -> g_out[2][16000][256]
    cudaFuncSetAttribute(gru_kernel, cudaFuncAttributeMaxDynamicSharedMemorySize, GRU_SMEM_BYTES);
    gru_kernel<<<dim3(8, 8, 2), 128, GRU_SMEM_BYTES>>>(xproj, g1whh, g2whh, g1bhh, g2bhh, gout);

    const float* outh = gout;
    const float* outd = gout + (long)MTOT * 256;

    // 5. per-branch logits
    launch_gemm_nt(outh, fccw, out,                 fccb, MTOT, NUM_Q, 256, 256, 256, NUM_Q, 0, 0, 0, 1);
    launch_gemm_nt(outd, fctw, out + 48000000L,     fctb, MTOT, NUM_Q, 256, 256, 256, NUM_Q, 0, 0, 0, 1);

    // 6. colsum of out_h (for (1-attn)@out_h trick)
    colsum_kernel<<<BATCH, 256>>>(outh, colsum);

    // 7. attention scores (batched): [32] x (500x500x256), stored ld 512
    launch_gemm_nt(outh, outd, attn, nullptr, SEQ, SEQ, 256, 256, 256, 512,
                   (long)SEQ * 256, (long)SEQ * 256, (long)SEQ * 512, BATCH);

    // 8. row softmax (+ zero pad cols 500..511)
    softmax_kernel<<<BATCH * SEQ, 256>>>(attn);

    // 9. apply attention (K=512 uses zero-padded attn cols):
    //    ens[:, :256]  = attn @ out_d
    //    ens[:, 256:]  = colsum_h - attn @ out_h
    launch_gemm_nn(attn, outd, ens, nullptr, SEQ, 256, 512, 512, 256, 512,
                   (long)SEQ * 512, (long)SEQ * 256, (long)SEQ * 512, BATCH);
    launch_gemm_nn_inv(attn, outh, ens + 256, colsum, SEQ, 256, 512, 512, 256, 512,
                       (long)SEQ * 512, (long)SEQ * 256, (long)SEQ * 512, BATCH);

    // 10. ensemble logits
    launch_gemm_nt(ens, fcew, out + 96000000L, fceb, MTOT, NUM_Q, 512, 512, 512, NUM_Q, 0, 0, 0, 1);
}

// round 2
// speedup vs baseline: 1.0035x; 1.0035x over previous
#include <cuda_runtime.h>
#include <cstdint>

// ---------------- problem constants ----------------
#define NUM_Q   3000
#define EMB     256
#define HID     256
#define BATCH   32
#define SEQ     500
#define MTOT    (BATCH * SEQ)        // 16000
#define KX      (2 * NUM_Q)          // 6000

// ---------------- scratch (static device globals; no runtime alloc) ----------------
__device__ float g_quesP[KX * 512];                 // packed [6000][512] = ques_h | ques_d
__device__ float g_xe[MTOT * 512];                  // [16000][512]  cols 0:256 = x_h, 256:512 = x_d
__device__ float g_xproj[2L * MTOT * 768];          // [2][16000][768]
__device__ float g_out[2L * MTOT * 256 + 4096];     // [2][16000][256] (+pad for K=512 overread)
__device__ float g_attn[BATCH * SEQ * 512];         // [32][500][512] (cols 500..511 zeroed)
__device__ float g_ens[MTOT * 512];                 // [16000][512]
__device__ float g_colsum[BATCH * 256];             // [32][256]

// ---------------- small helpers ----------------
__device__ __forceinline__ unsigned long long dupf2(float x) {
    unsigned long long r;
    asm("mov.b64 %0, {%1, %1};" : "=l"(r) : "f"(x));
    return r;
}
__device__ __forceinline__ float2 unpackf2(unsigned long long v) {
    float2 f;
    asm("mov.b64 {%0, %1}, %2;" : "=f"(f.x), "=f"(f.y) : "l"(v));
    return f;
}
#define FMA2(d, a, b) asm("fma.rn.f32x2 %0, %1, %2, %0;" : "+l"(d) : "l"(a), "l"(b))

__device__ __forceinline__ unsigned smem_u32(const void* p) {
    unsigned r;
    asm("{ .reg .u64 t; cvta.to.shared.u64 t, %1; cvt.u32.u64 %0, t; }" : "=r"(r) : "l"(p));
    return r;
}
#define CLUSTER_SYNC_() do { \
    asm volatile("barrier.cluster.arrive.aligned;" ::: "memory"); \
    asm volatile("barrier.cluster.wait.aligned;"   ::: "memory"); } while (0)

// ---------------- pack question tables ----------------
__global__ void packq_kernel(const float* __restrict__ qh, const float* __restrict__ qd,
                             float* __restrict__ dst) {
    int idx = blockIdx.x * 256 + threadIdx.x;           // over 6000*512
    int k = idx >> 9, c = idx & 511;
    float v = (c < 256) ? qh[k * 256 + c] : qd[k * 256 + (c - 256)];
    dst[idx] = v;
}

// ---------------- generic tiled fp32 GEMM, f32x2-packed ----------------
// C[m][n] = sum_k A[m][k] * B(k,n) (+bias[n])   BT=false: B row-major [K][N]
//                                               BT=true : B row-major [N][K]
// EPI==1: C[m][n] = colsum[z*256+n] - acc  (used for (1-attn)@out_h)
#define BM 128
#define BN 64
#define BKT 16

template <bool BT, int EPI>
__global__ __launch_bounds__(256)
void gemm_kernel(const float* __restrict__ A, const float* __restrict__ B,
                 float* __restrict__ C, const float* __restrict__ bias,
                 const float* __restrict__ colsum,
                 int M, int N, int K, int lda, int ldb, int ldc,
                 long sA, long sB, long sC) {
    __shared__ __align__(16) float As[BKT][BM + 4];   // stride 132 (16B-mult)
    __shared__ __align__(16) float Bs[BKT][BN + 4];   // stride 68  (16B-mult)

    const int z = blockIdx.z;
    A += (long)z * sA;  B += (long)z * sB;  C += (long)z * sC;

    const int row0 = blockIdx.y * BM;
    const int col0 = blockIdx.x * BN;
    const int tid = threadIdx.x;
    const int tx = tid & 15;        // 16 cols of threads (TN=4)
    const int ty = tid >> 4;        // 16 rows of threads (TM=8)

    unsigned long long acc2[4][4] = {};   // [row-pair][n] ; each = 2 fp32

    for (int k0 = 0; k0 < K; k0 += BKT) {
        // load A tile 128x16 (2 passes of float4)
        #pragma unroll
        for (int p = 0; p < 2; ++p) {
            int idx = tid + p * 256;          // 0..511
            int r = idx >> 2;
            int kq = (idx & 3) << 2;
            int gr = row0 + r;
            float4 v = make_float4(0.f, 0.f, 0.f, 0.f);
            if (gr < M) v = *(const float4*)(A + (long)gr * lda + k0 + kq);
            As[kq + 0][r] = v.x; As[kq + 1][r] = v.y;
            As[kq + 2][r] = v.z; As[kq + 3][r] = v.w;
        }
        // load B tile 16x64
        if (!BT) {
            int kk = tid >> 4;
            int nq = (tid & 15) << 2;
            int gn = col0 + nq;
            float4 v = make_float4(0.f, 0.f, 0.f, 0.f);
            if (gn < N) v = *(const float4*)(B + (long)(k0 + kk) * ldb + gn);
            *(float4*)&Bs[kk][nq] = v;
        } else {
            int r = tid >> 2;                 // n-row within tile
            int kq = (tid & 3) << 2;
            int gn = col0 + r;
            float4 v = make_float4(0.f, 0.f, 0.f, 0.f);
            if (gn < N) v = *(const float4*)(B + (long)gn * ldb + k0 + kq);
            Bs[kq + 0][r] = v.x; Bs[kq + 1][r] = v.y;
            Bs[kq + 2][r] = v.z; Bs[kq + 3][r] = v.w;
        }
        __syncthreads();

        #pragma unroll
        for (int kk = 0; kk < BKT; ++kk) {
            const ulonglong2 aA = *(const ulonglong2*)&As[kk][ty * 8];
            const ulonglong2 aB = *(const ulonglong2*)&As[kk][ty * 8 + 4];
            const float4 b4 = *(const float4*)&Bs[kk][tx * 4];
            unsigned long long bd0 = dupf2(b4.x), bd1 = dupf2(b4.y);
            unsigned long long bd2 = dupf2(b4.z), bd3 = dupf2(b4.w);
            FMA2(acc2[0][0], aA.x, bd0); FMA2(acc2[0][1], aA.x, bd1);
            FMA2(acc2[0][2], aA.x, bd2); FMA2(acc2[0][3], aA.x, bd3);
            FMA2(acc2[1][0], aA.y, bd0); FMA2(acc2[1][1], aA.y, bd1);
            FMA2(acc2[1][2], aA.y, bd2); FMA2(acc2[1][3], aA.y, bd3);
            FMA2(acc2[2][0], aB.x, bd0); FMA2(acc2[2][1], aB.x, bd1);
            FMA2(acc2[2][2], aB.x, bd2); FMA2(acc2[2][3], aB.x, bd3);
            FMA2(acc2[3][0], aB.y, bd0); FMA2(acc2[3][1], aB.y, bd1);
            FMA2(acc2[3][2], aB.y, bd2); FMA2(acc2[3][3], aB.y, bd3);
        }
        __syncthreads();
    }

    #pragma unroll
    for (int pi = 0; pi < 4; ++pi) {
        #pragma unroll
        for (int j = 0; j < 4; ++j) {
            int gn = col0 + tx * 4 + j;
            if (gn >= N) continue;
            float2 pv = unpackf2(acc2[pi][j]);
            float v0 = pv.x, v1 = pv.y;
            if (EPI == 1) {
                float cs = colsum[z * 256 + gn];
                v0 = cs - v0; v1 = cs - v1;
            } else if (bias) {
                float bv = bias[gn];
                v0 += bv; v1 += bv;
            }
            int r0 = row0 + ty * 8 + pi * 2;
            if (r0 < M)     C[(long)r0 * ldc + gn] = v0;
            if (r0 + 1 < M) C[(long)(r0 + 1) * ldc + gn] = v1;
        }
    }
}

// ---------------- GRU recurrence: cluster-of-8 persistent scan ----------------
// grid (8 ranks, 8 batch-groups, 2 grus), block 128. Each CTA owns 32 hidden
// units (96 W_hh rows: r/z/n gates), holds full h[4 batches][256] double-buffered,
// broadcasts its h_new slice to all 8 peers via DSMEM each step.
#define GRU_SMEM_FLOATS (96 * 260 + 96 + 2 * 1024 + 96 * 4)
#define GRU_SMEM_BYTES  (GRU_SMEM_FLOATS * 4)

__global__ void __cluster_dims__(8, 1, 1) __launch_bounds__(128, 1)
gru_kernel(const float* __restrict__ xproj,
           const float* __restrict__ whh1, const float* __restrict__ whh2,
           const float* __restrict__ bhh1, const float* __restrict__ bhh2,
           float* __restrict__ out) {
    extern __shared__ __align__(16) float sm[];
    float* Wm     = sm;                   // [96][260] padded rows
    float* bias_s = sm + 96 * 260;        // [96]
    float* h_s    = bias_s + 96;          // [2][4][256]
    float* gh_s   = h_s + 2048;           // [96][4]

    const int rank = blockIdx.x;
    const int bg   = blockIdx.y;
    const int gru  = blockIdx.z;
    const int tid  = threadIdx.x;

    const float* whh = gru ? whh2 : whh1;
    const float* bhh = gru ? bhh2 : bhh1;

    // load W slice: local row lr -> global row (lr/32)*256 + rank*32 + lr%32
    for (int idx = tid; idx < 96 * 256; idx += 128) {
        int lr = idx >> 8, k = idx & 255;
        int grow = ((lr >> 5) << 8) + (rank << 5) + (lr & 31);
        Wm[lr * 260 + k] = whh[grow * 256 + k];
    }
    if (tid < 96)
        bias_s[tid] = bhh[((tid >> 5) << 8) + (rank << 5) + (tid & 31)];
    for (int i = tid; i < 2048; i += 128) h_s[i] = 0.f;
    __syncthreads();
    CLUSTER_SYNC_();   // all peers' h buffers zeroed before any DSMEM writes

    const int b  = tid >> 5;            // phase-2 batch (0..3)
    const int jj = tid & 31;
    const int jg = (rank << 5) + jj;    // global hidden index
    const long mbase = (long)gru * MTOT + (long)bg * 4 * SEQ;
    const float* xp0 = xproj + mbase * 768;
    float* outp = out + mbase * 256;

    for (int t = 0; t < SEQ; ++t) {
        float* hc = h_s + ((t & 1) << 10);
        float* hn = h_s + (((t & 1) ^ 1) << 10);

        // prefetch this step's input projections (hidden behind phase 1)
        const float* xp = xp0 + ((long)b * SEQ + t) * 768;
        float xr = xp[jg], xz = xp[jg + 256], xn = xp[jg + 512];

        // phase 1: gh[row][b] = W[row] . h[b]  (96 rows x 4 batches)
        if (tid < 96) {
            const float* wrow = Wm + tid * 260;
            unsigned long long acc[4][2] = {};
            #pragma unroll 16
            for (int k = 0; k < 256; k += 4) {
                ulonglong2 w2 = *(const ulonglong2*)(wrow + k);
                #pragma unroll
                for (int bb = 0; bb < 4; ++bb) {
                    ulonglong2 h2 = *(const ulonglong2*)(hc + (bb << 8) + k);
                    FMA2(acc[bb][0], w2.x, h2.x);
                    FMA2(acc[bb][1], w2.y, h2.y);
                }
            }
            #pragma unroll
            for (int bb = 0; bb < 4; ++bb) {
                float2 p = unpackf2(acc[bb][0]);
                float2 q = unpackf2(acc[bb][1]);
                gh_s[tid * 4 + bb] = p.x + p.y + q.x + q.y + bias_s[tid];
            }
        }
        __syncthreads();

        // phase 2: gates + state update for (b, jj)
        {
            float ghr = gh_s[jj * 4 + b];
            float ghz = gh_s[(32 + jj) * 4 + b];
            float ghn = gh_s[(64 + jj) * 4 + b];
            float r = 1.f / (1.f + __expf(-(xr + ghr)));
            float z = 1.f / (1.f + __expf(-(xz + ghz)));
            float n = tanhf(xn + r * ghn);
            float hnew = (1.f - z) * n + z * hc[(b << 8) + jg];
            outp[((long)b * SEQ + t) * 256 + jg] = hnew;

            unsigned laddr = smem_u32(hn + (b << 8) + jg);
            unsigned hbits = __float_as_uint(hnew);
            #pragma unroll
            for (int rd = 0; rd < 8; ++rd) {
                unsigned raddr;
                asm volatile("mapa.shared::cluster.u32 %0, %1, %2;"
                             : "=r"(raddr) : "r"(laddr), "r"(rd));
                asm volatile("st.shared::cluster.b32 [%0], %1;"
                             :: "r"(raddr), "r"(hbits) : "memory");
            }
        }
        CLUSTER_SYNC_();   // h_new visible everywhere; also block-level barrier
    }
}

// ---------------- softmax over rows of 500 (ld 512), zero-pads cols 500..511 ----------------
__global__ void softmax_kernel(float* __restrict__ attn) {
    __shared__ float red[8];
    float* p = attn + (long)blockIdx.x * 512;
    int tid = threadIdx.x;
    float v1 = (tid < 500)       ? p[tid]       : -1e30f;
    float v2 = (tid + 256 < 500) ? p[tid + 256] : -1e30f;

    float m = fmaxf(v1, v2);
    #pragma unroll
    for (int o = 16; o; o >>= 1) m = fmaxf(m, __shfl_xor_sync(~0u, m, o));
    if ((tid & 31) == 0) red[tid >> 5] = m;
    __syncthreads();
    if (tid == 0) {
        float mm = red[0];
        #pragma unroll
        for (int i = 1; i < 8; ++i) mm = fmaxf(mm, red[i]);
        red[0] = mm;
    }
    __syncthreads();
    m = red[0];
    __syncthreads();

    float e1 = (tid < 500)       ? __expf(v1 - m) : 0.f;
    float e2 = (tid + 256 < 500) ? __expf(v2 - m) : 0.f;
    float s = e1 + e2;
    #pragma unroll
    for (int o = 16; o; o >>= 1) s += __shfl_xor_sync(~0u, s, o);
    if ((tid & 31) == 0) red[tid >> 5] = s;
    __syncthreads();
    if (tid == 0) {
        float ss = 0.f;
        #pragma unroll
        for (int i = 0; i < 8; ++i) ss += red[i];
        red[0] = ss;
    }
    __syncthreads();
    float inv = 1.f / red[0];

    if (tid < 500) p[tid] = e1 * inv;
    p[tid + 256] = e2 * inv;   // writes exact 0 to cols 500..511
}

// ---------------- column sum of out_h per batch: colsum[b][j] = sum_t out_h[b,t,j] ----------------
__global__ void colsum_kernel(const float* __restrict__ outh, float* __restrict__ cs) {
    int b = blockIdx.x, j = threadIdx.x;
    const float* p = outh + (long)b * SEQ * 256 + j;
    float s = 0.f;
    for (int t = 0; t < SEQ; ++t) s += p[(long)t * 256];
    cs[b * 256 + j] = s;
}

// ---------------- host orchestration ----------------
static void launch_gemm_nn(const float* A, const float* B, float* C, const float* bias,
                           int M, int N, int K, int lda, int ldb, int ldc,
                           long sA, long sB, long sC, int batch) {
    dim3 grid((N + BN - 1) / BN, (M + BM - 1) / BM, batch);
    gemm_kernel<false, 0><<<grid, 256>>>(A, B, C, bias, nullptr, M, N, K, lda, ldb, ldc, sA, sB, sC);
}
static void launch_gemm_nt(const float* A, const float* B, float* C, const float* bias,
                           int M, int N, int K, int lda, int ldb, int ldc,
                           long sA, long sB, long sC, int batch) {
    dim3 grid((N + BN - 1) / BN, (M + BM - 1) / BM, batch);
    gemm_kernel<true, 0><<<grid, 256>>>(A, B, C, bias, nullptr, M, N, K, lda, ldb, ldc, sA, sB, sC);
}
static void launch_gemm_nn_inv(const float* A, const float* B, float* C, const float* colsum,
                               int M, int N, int K, int lda, int ldb, int ldc,
                               long sA, long sB, long sC, int batch) {
    dim3 grid((N + BN - 1) / BN, (M + BM - 1) / BM, batch);
    gemm_kernel<false, 1><<<grid, 256>>>(A, B, C, nullptr, colsum, M, N, K, lda, ldb, ldc, sA, sB, sC);
}

extern "C" void kernel_launch(void* const* d_in, const int* in_sizes, int n_in,
                              void* d_out, int out_size) {
    const float* x      = (const float*)d_in[0];
    const float* qh     = (const float*)d_in[1];
    const float* qd     = (const float*)d_in[2];
    const float* g1wih  = (const float*)d_in[3];
    const float* g1whh  = (const float*)d_in[4];
    const float* g1bih  = (const float*)d_in[5];
    const float* g1bhh  = (const float*)d_in[6];
    const float* g2wih  = (const float*)d_in[7];
    const float* g2whh  = (const float*)d_in[8];
    const float* g2bih  = (const float*)d_in[9];
    const float* g2bhh  = (const float*)d_in[10];
    const float* fccw   = (const float*)d_in[11];
    const float* fccb   = (const float*)d_in[12];
    const float* fctw   = (const float*)d_in[13];
    const float* fctb   = (const float*)d_in[14];
    const float* fcew   = (const float*)d_in[15];
    const float* fceb   = (const float*)d_in[16];
    float* out = (float*)d_out;

    float *quesP, *xe, *xproj, *gout, *attn, *ens, *colsum;
    cudaGetSymbolAddress((void**)&quesP,  g_quesP);
    cudaGetSymbolAddress((void**)&xe,     g_xe);
    cudaGetSymbolAddress((void**)&xproj,  g_xproj);
    cudaGetSymbolAddress((void**)&gout,   g_out);
    cudaGetSymbolAddress((void**)&attn,   g_attn);
    cudaGetSymbolAddress((void**)&ens,    g_ens);
    cudaGetSymbolAddress((void**)&colsum, g_colsum);

    // 1. pack question tables: [6000][512]
    packq_kernel<<<(KX * 512) / 256, 256>>>(qh, qd, quesP);

    // 2. embeddings: g_xe[16000][512] = x @ quesP   (reads x once)
    launch_gemm_nn(x, quesP, xe, nullptr, MTOT, 512, KX, KX, 512, 512, 0, 0, 0, 1);

    // 3. input projections: x_proj = x_emb @ w_ih^T + b_ih   -> [2][16000][768]
    launch_gemm_nt(xe,       g1wih, xproj,                      g1bih, MTOT, 768, 256, 512, 256, 768, 0, 0, 0, 1);
    launch_gemm_nt(xe + 256, g2wih, xproj + (long)MTOT * 768,   g2bih, MTOT, 768, 256, 512, 256, 768, 0, 0, 0, 1);

    // 4. GRU scans (both GRUs, all batches) -> g_out[2][16000][256]
    cudaFuncSetAttribute(gru_kernel, cudaFuncAttributeMaxDynamicSharedMemorySize, GRU_SMEM_BYTES);
    gru_kernel<<<dim3(8, 8, 2), 128, GRU_SMEM_BYTES>>>(xproj, g1whh, g2whh, g1bhh, g2bhh, gout);

    const float* outh = gout;
    const float* outd = gout + (long)MTOT * 256;

    // 5. per-branch logits
    launch_gemm_nt(outh, fccw, out,                 fccb, MTOT, NUM_Q, 256, 256, 256, NUM_Q, 0, 0, 0, 1);
    launch_gemm_nt(outd, fctw, out + 48000000L,     fctb, MTOT, NUM_Q, 256, 256, 256, NUM_Q, 0, 0, 0, 1);

    // 6. colsum of out_h (for (1-attn)@out_h trick)
    colsum_kernel<<<BATCH, 256>>>(outh, colsum);

    // 7. attention scores (batched): [32] x (500x500x256), stored ld 512
    launch_gemm_nt(outh, outd, attn, nullptr, SEQ, SEQ, 256, 256, 256, 512,
                   (long)SEQ * 256, (long)SEQ * 256, (long)SEQ * 512, BATCH);

    // 8. row softmax (+ zero pad cols 500..511)
    softmax_kernel<<<BATCH * SEQ, 256>>>(attn);

    // 9. apply attention (K=512 uses zero-padded attn cols):
    //    ens[:, :256]  = attn @ out_d
    //    ens[:, 256:]  = colsum_h - attn @ out_h
    launch_gemm_nn(attn, outd, ens, nullptr, SEQ, 256, 512, 512, 256, 512,
                   (long)SEQ * 512, (long)SEQ * 256, (long)SEQ * 512, BATCH);
    launch_gemm_nn_inv(attn, outh, ens + 256, colsum, SEQ, 256, 512, 512, 256, 512,
                       (long)SEQ * 512, (long)SEQ * 256, (long)SEQ * 512, BATCH);

    // 10. ensemble logits
    launch_gemm_nt(ens, fcew, out + 96000000L, fceb, MTOT, NUM_Q, 512, 512, 512, NUM_Q, 0, 0, 0, 1);
}

// round 4
// speedup vs baseline: 1.0690x; 1.0653x over previous
#include <cuda_runtime.h>
#include <cuda_bf16.h>
#include <cstdint>

#define NUM_Q 3000
#define EMB 256
#define HID 256
#define BATCH 32
#define SEQ 500
#define MTOT (BATCH * SEQ)
#define KX (2 * NUM_Q)

// ---------------- scratch ----------------
__device__ float g_qT[512 * KX];                     // [512][6000] tables^T
__device__ float g_xe[(size_t)MTOT * 512];           // [16000][512]
__device__ float g_xproj[2ll * MTOT * 768];
__device__ float g_out[2ll * MTOT * 256 + 4096];
__device__ float g_attn[(size_t)BATCH * SEQ * 512];
__device__ float g_ens[(size_t)MTOT * 512];
__device__ float g_colsum[BATCH * 256];

// ---------------- helpers ----------------
__device__ __forceinline__ unsigned long long dupf2(float x) {
    unsigned long long r; asm("mov.b64 %0, {%1, %1};" : "=l"(r) : "f"(x)); return r;
}
__device__ __forceinline__ float2 unpackf2(unsigned long long v) {
    float2 f; asm("mov.b64 {%0, %1}, %2;" : "=f"(f.x), "=f"(f.y) : "l"(v)); return f;
}
#define FMA2(d, a, b) asm("fma.rn.f32x2 %0, %1, %2, %0;" : "+l"(d) : "l"(a), "l"(b))

__device__ __forceinline__ unsigned smem_u32(const void* p) {
    unsigned r;
    asm("{ .reg .u64 t; cvta.to.shared.u64 t, %1; cvt.u32.u64 %0, t; }" : "=r"(r) : "l"(p));
    return r;
}
#define CLUSTER_SYNC_() do { \
    asm volatile("barrier.cluster.arrive.aligned;" ::: "memory"); \
    asm volatile("barrier.cluster.wait.aligned;"   ::: "memory"); } while (0)

#define LDSM4(r, addr) asm volatile( \
    "ldmatrix.sync.aligned.m8n8.x4.shared.b16 {%0,%1,%2,%3}, [%4];" \
    : "=r"((r)[0]), "=r"((r)[1]), "=r"((r)[2]), "=r"((r)[3]) : "r"(addr))

#define MMA_BF16(c, a, b0, b1) asm volatile( \
    "mma.sync.aligned.m16n8k16.row.col.f32.bf16.bf16.f32 " \
    "{%0,%1,%2,%3}, {%4,%5,%6,%7}, {%8,%9}, {%0,%1,%2,%3};" \
    : "+f"((c)[0]), "+f"((c)[1]), "+f"((c)[2]), "+f"((c)[3]) \
    : "r"((a)[0]), "r"((a)[1]), "r"((a)[2]), "r"((a)[3]), "r"(b0), "r"(b1))

// ---------------- pack question tables transposed: qT[c][k] ----------------
__global__ void packqT_kernel(const float* __restrict__ qh, const float* __restrict__ qd,
                              float* __restrict__ dst) {
    __shared__ float t[32][33];
    int kb = blockIdx.x * 32, cb = blockIdx.y * 32;
    const float* src = (cb < 256) ? qh : qd;
    int cc0 = cb & 255;
    int x = threadIdx.x, y = threadIdx.y;
    for (int yy = y; yy < 32; yy += 8) {
        int k = kb + yy;
        t[yy][x] = (k < KX) ? src[(long)k * 256 + cc0 + x] : 0.f;
    }
    __syncthreads();
    if (kb + x < KX)
        for (int yy = y; yy < 32; yy += 8)
            dst[(long)(cb + yy) * KX + kb + x] = t[x][yy];
}

// ---------------- bf16-split tensor-core NT GEMM ----------------
// C[M,N] = A[M,K] @ B[N,K]^T (+bias), fp32 in/out.
// Split each operand a = hi(bf16) + lo(bf16); accumulate hi*hi + lo*hi + hi*lo.
// Block 256 thr (8 warps as 4m x 2n, warp tile 32x64), tile 128x128x32.
__global__ __launch_bounds__(256)
void mma_gemm(const float* __restrict__ A, const float* __restrict__ B,
              float* __restrict__ C, const float* __restrict__ bias,
              int M, int N, int K, int lda, int ldb, int ldc,
              long sA, long sB, long sC) {
    // rows padded to 40 halves (80B): 16B-bank conflict-free for ldmatrix
    __shared__ __align__(16) __nv_bfloat16 sm[4][128 * 40];  // Ahi, Alo, Bhi, Blo

    const int z = blockIdx.z;
    A += (long)z * sA; B += (long)z * sB; C += (long)z * sC;
    const int row0 = blockIdx.y * 128, col0 = blockIdx.x * 128;
    const int tid = threadIdx.x;
    const int lane = tid & 31, wid = tid >> 5;
    const int wm0 = (wid & 3) * 32, wn0 = (wid >> 2) * 64;

    // staging indices: 2 threads per row, 16 floats each
    const int wrow = tid >> 1;
    const int wcol = (tid & 1) << 4;
    int arow = row0 + wrow; if (arow >= M) arow = M - 1;
    int brow = col0 + wrow; if (brow >= N) brow = N - 1;
    const float* pa = A + (long)arow * lda;
    const float* pb = B + (long)brow * ldb;

    float c[2][8][4];
    #pragma unroll
    for (int a = 0; a < 2; ++a)
        #pragma unroll
        for (int b = 0; b < 8; ++b)
            #pragma unroll
            for (int d = 0; d < 4; ++d) c[a][b][d] = 0.f;

    for (int k0 = 0; k0 < K; k0 += 32) {
        __syncthreads();
        #pragma unroll
        for (int half = 0; half < 2; ++half) {
            const float* ps = half ? pb : pa;
            __nv_bfloat16* dh = half ? sm[2] : sm[0];
            __nv_bfloat16* dl = half ? sm[3] : sm[1];
            #pragma unroll
            for (int cq = 0; cq < 4; ++cq) {
                int k = k0 + wcol + cq * 4;
                float4 v;
                if (k + 3 < K) v = *(const float4*)(ps + k);
                else {
                    v.x = (k     < K) ? ps[k]     : 0.f;
                    v.y = (k + 1 < K) ? ps[k + 1] : 0.f;
                    v.z = (k + 2 < K) ? ps[k + 2] : 0.f;
                    v.w = (k + 3 < K) ? ps[k + 3] : 0.f;
                }
                __nv_bfloat162 h01 = __floats2bfloat162_rn(v.x, v.y);
                __nv_bfloat162 h23 = __floats2bfloat162_rn(v.z, v.w);
                float2 f01 = __bfloat1622float2(h01);
                float2 f23 = __bfloat1622float2(h23);
                __nv_bfloat162 l01 = __floats2bfloat162_rn(v.x - f01.x, v.y - f01.y);
                __nv_bfloat162 l23 = __floats2bfloat162_rn(v.z - f23.x, v.w - f23.y);
                int off = wrow * 40 + wcol + cq * 4;
                *(__nv_bfloat162*)(dh + off)     = h01;
                *(__nv_bfloat162*)(dh + off + 2) = h23;
                *(__nv_bfloat162*)(dl + off)     = l01;
                *(__nv_bfloat162*)(dl + off + 2) = l23;
            }
        }
        __syncthreads();

        #pragma unroll
        for (int kk = 0; kk < 2; ++kk) {
            // B fragments: 4 ldmatrix.x4 cover 8 n-tiles (hi and lo)
            uint32_t bh[4][4], bl[4][4];
            #pragma unroll
            for (int nt2 = 0; nt2 < 4; ++nt2) {
                int rb = wn0 + nt2 * 16 + (lane & 7) + ((lane >> 4) << 3);
                int cb2 = kk * 16 + (((lane >> 3) & 1) << 3);
                LDSM4(bh[nt2], smem_u32(sm[2] + rb * 40 + cb2));
                LDSM4(bl[nt2], smem_u32(sm[3] + rb * 40 + cb2));
            }
            #pragma unroll
            for (int mt = 0; mt < 2; ++mt) {
                int ra = wm0 + mt * 16 + (lane & 15);
                int ca = kk * 16 + ((lane >> 4) << 3);
                uint32_t ah[4], al[4];
                LDSM4(ah, smem_u32(sm[0] + ra * 40 + ca));
                LDSM4(al, smem_u32(sm[1] + ra * 40 + ca));
                #pragma unroll
                for (int nt2 = 0; nt2 < 4; ++nt2) {
                    #pragma unroll
                    for (int hh = 0; hh < 2; ++hh) {
                        float* cc = c[mt][nt2 * 2 + hh];
                        uint32_t b0h = bh[nt2][hh * 2], b1h = bh[nt2][hh * 2 + 1];
                        MMA_BF16(cc, ah, b0h, b1h);
                        MMA_BF16(cc, al, b0h, b1h);
                        MMA_BF16(cc, ah, bl[nt2][hh * 2], bl[nt2][hh * 2 + 1]);
                    }
                }
            }
        }
    }

    // epilogue: direct fp32 stores (n0 always even; ldc even -> 8B aligned)
    const int g = lane >> 2, tg = lane & 3;
    #pragma unroll
    for (int mt = 0; mt < 2; ++mt)
        #pragma unroll
        for (int nt = 0; nt < 8; ++nt) {
            int m0 = row0 + wm0 + mt * 16 + g;
            int n0 = col0 + wn0 + nt * 8 + tg * 2;
            if (n0 < N) {
                float b0 = bias ? bias[n0] : 0.f;
                float b1 = bias ? bias[n0 + 1] : 0.f;
                if (m0 < M)
                    *(float2*)&C[(long)m0 * ldc + n0] =
                        make_float2(c[mt][nt][0] + b0, c[mt][nt][1] + b1);
                if (m0 + 8 < M)
                    *(float2*)&C[(long)(m0 + 8) * ldc + n0] =
                        make_float2(c[mt][nt][2] + b0, c[mt][nt][3] + b1);
            }
        }
}

// ---------------- SIMT fp32 GEMM (attention apply path) ----------------
#define BM 128
#define BN 64
#define BKT 16

template <int EPI>
__global__ __launch_bounds__(256)
void gemm_kernel(const float* __restrict__ A, const float* __restrict__ B,
                 float* __restrict__ C, const float* __restrict__ colsum,
                 int M, int N, int K, int lda, int ldb, int ldc,
                 long sA, long sB, long sC) {
    __shared__ __align__(16) float As[BKT][BM + 4];
    __shared__ __align__(16) float Bs[BKT][BN + 4];
    const int z = blockIdx.z;
    A += (long)z * sA; B += (long)z * sB; C += (long)z * sC;
    const int row0 = blockIdx.y * BM, col0 = blockIdx.x * BN;
    const int tid = threadIdx.x, tx = tid & 15, ty = tid >> 4;
    unsigned long long acc2[4][4] = {};

    for (int k0 = 0; k0 < K; k0 += BKT) {
        #pragma unroll
        for (int p = 0; p < 2; ++p) {
            int idx = tid + p * 256;
            int r = idx >> 2, kq = (idx & 3) << 2, gr = row0 + r;
            float4 v = make_float4(0.f, 0.f, 0.f, 0.f);
            if (gr < M) v = *(const float4*)(A + (long)gr * lda + k0 + kq);
            As[kq + 0][r] = v.x; As[kq + 1][r] = v.y;
            As[kq + 2][r] = v.z; As[kq + 3][r] = v.w;
        }
        {
            int kk = tid >> 4, nq = (tid & 15) << 2, gn = col0 + nq;
            float4 v = make_float4(0.f, 0.f, 0.f, 0.f);
            if (gn < N) v = *(const float4*)(B + (long)(k0 + kk) * ldb + gn);
            *(float4*)&Bs[kk][nq] = v;
        }
        __syncthreads();
        #pragma unroll
        for (int kk = 0; kk < BKT; ++kk) {
            const ulonglong2 aA = *(const ulonglong2*)&As[kk][ty * 8];
            const ulonglong2 aB = *(const ulonglong2*)&As[kk][ty * 8 + 4];
            const float4 b4 = *(const float4*)&Bs[kk][tx * 4];
            unsigned long long bd0 = dupf2(b4.x), bd1 = dupf2(b4.y);
            unsigned long long bd2 = dupf2(b4.z), bd3 = dupf2(b4.w);
            FMA2(acc2[0][0], aA.x, bd0); FMA2(acc2[0][1], aA.x, bd1);
            FMA2(acc2[0][2], aA.x, bd2); FMA2(acc2[0][3], aA.x, bd3);
            FMA2(acc2[1][0], aA.y, bd0); FMA2(acc2[1][1], aA.y, bd1);
            FMA2(acc2[1][2], aA.y, bd2); FMA2(acc2[1][3], aA.y, bd3);
            FMA2(acc2[2][0], aB.x, bd0); FMA2(acc2[2][1], aB.x, bd1);
            FMA2(acc2[2][2], aB.x, bd2); FMA2(acc2[2][3], aB.x, bd3);
            FMA2(acc2[3][0], aB.y, bd0); FMA2(acc2[3][1], aB.y, bd1);
            FMA2(acc2[3][2], aB.y, bd2); FMA2(acc2[3][3], aB.y, bd3);
        }
        __syncthreads();
    }
    #pragma unroll
    for (int pi = 0; pi < 4; ++pi)
        #pragma unroll
        for (int j = 0; j < 4; ++j) {
            int gn = col0 + tx * 4 + j;
            if (gn >= N) continue;
            float2 pv = unpackf2(acc2[pi][j]);
            float v0 = pv.x, v1 = pv.y;
            if (EPI == 1) {
                float cs = colsum[z * 256 + gn];
                v0 = cs - v0; v1 = cs - v1;
            }
            int r0 = row0 + ty * 8 + pi * 2;
            if (r0 < M)     C[(long)r0 * ldc + gn] = v0;
            if (r0 + 1 < M) C[(long)(r0 + 1) * ldc + gn] = v1;
        }
}

// ---------------- GRU recurrence: cluster-of-8 persistent scan ----------------
#define GRU_SMEM_FLOATS (96 * 260 + 96 + 2 * 1024 + 96 * 4)
#define GRU_SMEM_BYTES  (GRU_SMEM_FLOATS * 4)

__global__ void __cluster_dims__(8, 1, 1) __launch_bounds__(128, 1)
gru_kernel(const float* __restrict__ xproj,
           const float* __restrict__ whh1, const float* __restrict__ whh2,
           const float* __restrict__ bhh1, const float* __restrict__ bhh2,
           float* __restrict__ out) {
    extern __shared__ __align__(16) float sm[];
    float* Wm = sm;
    float* bias_s = sm + 96 * 260;
    float* h_s = bias_s + 96;
    float* gh_s = h_s + 2048;

    const int rank = blockIdx.x, bg = blockIdx.y, gru = blockIdx.z;
    const int tid = threadIdx.x;
    const float* whh = gru ? whh2 : whh1;
    const float* bhh = gru ? bhh2 : bhh1;

    for (int idx = tid; idx < 96 * 256; idx += 128) {
        int lr = idx >> 8, k = idx & 255;
        int grow = ((lr >> 5) << 8) + (rank << 5) + (lr & 31);
        Wm[lr * 260 + k] = whh[grow * 256 + k];
    }
    if (tid < 96)
        bias_s[tid] = bhh[((tid >> 5) << 8) + (rank << 5) + (tid & 31)];
    for (int i = tid; i < 2048; i += 128) h_s[i] = 0.f;
    __syncthreads();
    CLUSTER_SYNC_();

    const int b = tid >> 5, jj = tid & 31;
    const int jg = (rank << 5) + jj;
    const long mbase = (long)gru * MTOT + (long)bg * 4 * SEQ;
    const float* xp0 = xproj + mbase * 768;
    float* outp = out + mbase * 256;

    for (int t = 0; t < SEQ; ++t) {
        float* hc = h_s + ((t & 1) << 10);
        float* hn = h_s + (((t & 1) ^ 1) << 10);
        const float* xp = xp0 + ((long)b * SEQ + t) * 768;
        float xr = xp[jg], xz = xp[jg + 256], xn = xp[jg + 512];

        if (tid < 96) {
            const float* wrow = Wm + tid * 260;
            unsigned long long acc[4][2] = {};
            #pragma unroll 16
            for (int k = 0; k < 256; k += 4) {
                ulonglong2 w2 = *(const ulonglong2*)(wrow + k);
                #pragma unroll
                for (int bb = 0; bb < 4; ++bb) {
                    ulonglong2 h2 = *(const ulonglong2*)(hc + (bb << 8) + k);
                    FMA2(acc[bb][0], w2.x, h2.x);
                    FMA2(acc[bb][1], w2.y, h2.y);
                }
            }
            #pragma unroll
            for (int bb = 0; bb < 4; ++bb) {
                float2 p = unpackf2(acc[bb][0]);
                float2 q = unpackf2(acc[bb][1]);
                gh_s[tid * 4 + bb] = p.x + p.y + q.x + q.y + bias_s[tid];
            }
        }
        __syncthreads();
        {
            float ghr = gh_s[jj * 4 + b];
            float ghz = gh_s[(32 + jj) * 4 + b];
            float ghn = gh_s[(64 + jj) * 4 + b];
            float r = 1.f / (1.f + __expf(-(xr + ghr)));
            float z = 1.f / (1.f + __expf(-(xz + ghz)));
            float n = tanhf(xn + r * ghn);
            float hnew = (1.f - z) * n + z * hc[(b << 8) + jg];
            outp[((long)b * SEQ + t) * 256 + jg] = hnew;
            unsigned laddr = smem_u32(hn + (b << 8) + jg);
            unsigned hbits = __float_as_uint(hnew);
            #pragma unroll
            for (int rd = 0; rd < 8; ++rd) {
                unsigned raddr;
                asm volatile("mapa.shared::cluster.u32 %0, %1, %2;" : "=r"(raddr) : "r"(laddr), "r"(rd));
                asm volatile("st.shared::cluster.b32 [%0], %1;" :: "r"(raddr), "r"(hbits) : "memory");
            }
        }
        CLUSTER_SYNC_();
    }
}

// ---------------- softmax rows of 500 (ld 512; zeroes cols 500..511) ----------------
__global__ void softmax_kernel(float* __restrict__ attn) {
    __shared__ float red[8];
    float* p = attn + (long)blockIdx.x * 512;
    int tid = threadIdx.x;
    float v1 = (tid < 500) ? p[tid] : -1e30f;
    float v2 = (tid + 256 < 500) ? p[tid + 256] : -1e30f;
    float m = fmaxf(v1, v2);
    #pragma unroll
    for (int o = 16; o; o >>= 1) m = fmaxf(m, __shfl_xor_sync(~0u, m, o));
    if ((tid & 31) == 0) red[tid >> 5] = m;
    __syncthreads();
    if (tid == 0) {
        float mm = red[0];
        #pragma unroll
        for (int i = 1; i < 8; ++i) mm = fmaxf(mm, red[i]);
        red[0] = mm;
    }
    __syncthreads();
    m = red[0];
    __syncthreads();
    float e1 = (tid < 500) ? __expf(v1 - m) : 0.f;
    float e2 = (tid + 256 < 500) ? __expf(v2 - m) : 0.f;
    float s = e1 + e2;
    #pragma unroll
    for (int o = 16; o; o >>= 1) s += __shfl_xor_sync(~0u, s, o);
    if ((tid & 31) == 0) red[tid >> 5] = s;
    __syncthreads();
    if (tid == 0) {
        float ss = 0.f;
        #pragma unroll
        for (int i = 0; i < 8; ++i) ss += red[i];
        red[0] = ss;
    }
    __syncthreads();
    float inv = 1.f / red[0];
    if (tid < 500) p[tid] = e1 * inv;
    p[tid + 256] = e2 * inv;
}

__global__ void colsum_kernel(const float* __restrict__ outh, float* __restrict__ cs) {
    int b = blockIdx.x, j = threadIdx.x;
    const float* p = outh + (long)b * SEQ * 256 + j;
    float s = 0.f;
    for (int t = 0; t < SEQ; ++t) s += p[(long)t * 256];
    cs[b * 256 + j] = s;
}

// ---------------- host ----------------
static void launch_mma(const float* A, const float* B, float* C, const float* bias,
                       int M, int N, int K, int lda, int ldb, int ldc,
                       long sA, long sB, long sC, int batch) {
    dim3 grid((N + 127) / 128, (M + 127) / 128, batch);
    mma_gemm<<<grid, 256>>>(A, B, C, bias, M, N, K, lda, ldb, ldc, sA, sB, sC);
}

extern "C" void kernel_launch(void* const* d_in, const int* in_sizes, int n_in,
                              void* d_out, int out_size) {
    const float* x     = (const float*)d_in[0];
    const float* qh    = (const float*)d_in[1];
    const float* qd    = (const float*)d_in[2];
    const float* g1wih = (const float*)d_in[3];
    const float* g1whh = (const float*)d_in[4];
    const float* g1bih = (const float*)d_in[5];
    const float* g1bhh = (const float*)d_in[6];
    const float* g2wih = (const float*)d_in[7];
    const float* g2whh = (const float*)d_in[8];
    const float* g2bih = (const float*)d_in[9];
    const float* g2bhh = (const float*)d_in[10];
    const float* fccw  = (const float*)d_in[11];
    const float* fccb  = (const float*)d_in[12];
    const float* fctw  = (const float*)d_in[13];
    const float* fctb  = (const float*)d_in[14];
    const float* fcew  = (const float*)d_in[15];
    const float* fceb  = (const float*)d_in[16];
    float* out = (float*)d_out;

    float *qT, *xe, *xproj, *gout, *attn, *ens, *colsum;
    cudaGetSymbolAddress((void**)&qT, g_qT);
    cudaGetSymbolAddress((void**)&xe, g_xe);
    cudaGetSymbolAddress((void**)&xproj, g_xproj);
    cudaGetSymbolAddress((void**)&gout, g_out);
    cudaGetSymbolAddress((void**)&attn, g_attn);
    cudaGetSymbolAddress((void**)&ens, g_ens);
    cudaGetSymbolAddress((void**)&colsum, g_colsum);

    cudaFuncSetAttribute(gru_kernel, cudaFuncAttributeMaxDynamicSharedMemorySize, GRU_SMEM_BYTES);

    // 1. transpose question tables -> qT[512][6000]
    packqT_kernel<<<dim3((KX + 31) / 32, 16), dim3(32, 8)>>>(qh, qd, qT);

    // 2. embeddings: xe[16000][512] = x @ qT^T   (bf16-split MMA, K=6000)
    launch_mma(x, qT, xe, nullptr, MTOT, 512, KX, KX, KX, 512, 0, 0, 0, 1);

    // 3. input projections [2][16000][768]
    launch_mma(xe,       g1wih, xproj,                    g1bih, MTOT, 768, 256, 512, 256, 768, 0, 0, 0, 1);
    launch_mma(xe + 256, g2wih, xproj + (long)MTOT * 768, g2bih, MTOT, 768, 256, 512, 256, 768, 0, 0, 0, 1);

    // 4. GRU scans
    gru_kernel<<<dim3(8, 8, 2), 128, GRU_SMEM_BYTES>>>(xproj, g1whh, g2whh, g1bhh, g2bhh, gout);

    const float* outh = gout;
    const float* outd = gout + (long)MTOT * 256;

    // 5. per-branch logits
    launch_mma(outh, fccw, out,             fccb, MTOT, NUM_Q, 256, 256, 256, NUM_Q, 0, 0, 0, 1);
    launch_mma(outd, fctw, out + 48000000L, fctb, MTOT, NUM_Q, 256, 256, 256, NUM_Q, 0, 0, 0, 1);

    // 6. colsum for (1-attn)@out_h trick
    colsum_kernel<<<BATCH, 256>>>(outh, colsum);

    // 7. attention scores (batched): [32] x (500x500x256), ldc 512
    launch_mma(outh, outd, attn, nullptr, SEQ, SEQ, 256, 256, 256, 512,
               500L * 256, 500L * 256, 500L * 512, BATCH);

    // 8. softmax (+ zero pad cols 500..511)
    softmax_kernel<<<BATCH * SEQ, 256>>>(attn);

    // 9. apply attention (fp32 SIMT):
    //    ens[:, :256] = attn @ out_d ; ens[:, 256:] = colsum_h - attn @ out_h
    {
        dim3 grid((256 + BN - 1) / BN, (SEQ + BM - 1) / BM, BATCH);
        gemm_kernel<0><<<grid, 256>>>(attn, outd, ens, nullptr,
            SEQ, 256, 512, 512, 256, 512, 500L * 512, 500L * 256, 500L * 512);
        gemm_kernel<1><<<grid, 256>>>(attn, outh, ens + 256, colsum,
            SEQ, 256, 512, 512, 256, 512, 500L * 512, 500L * 256, 500L * 512);
    }

    // 10. ensemble logits
    launch_mma(ens, fcew, out + 96000000L, fceb, MTOT, NUM_Q, 512, 512, 512, NUM_Q, 0, 0, 0, 1);
}

// round 5
// speedup vs baseline: 1.3797x; 1.2906x over previous
#include <cuda_runtime.h>
#include <cuda_bf16.h>
#include <cstdint>

#define NUM_Q 3000
#define BATCH 32
#define SEQ 500
#define MTOT (BATCH * SEQ)
#define KX (2 * NUM_Q)

typedef __nv_bfloat16 bf16;
typedef __nv_bfloat162 bf162;

// ---------------- scratch (bf16 hi/lo planes) ----------------
__device__ __align__(256) bf16 g_xh[(size_t)MTOT * KX + 64];
__device__ __align__(256) bf16 g_xl[(size_t)MTOT * KX + 64];
__device__ __align__(256) bf16 g_qTh[512 * KX + 64];
__device__ __align__(256) bf16 g_qTl[512 * KX + 64];
__device__ __align__(256) bf16 g_wh[3465216];
__device__ __align__(256) bf16 g_wl[3465216];
__device__ __align__(256) bf16 g_xeh[(size_t)MTOT * 512];
__device__ __align__(256) bf16 g_xel[(size_t)MTOT * 512];
__device__ __align__(256) bf16 g_gh[2ll * MTOT * 256];
__device__ __align__(256) bf16 g_gl[2ll * MTOT * 256];
__device__ __align__(256) bf16 g_gTh[2ll * 32 * 256 * 512];
__device__ __align__(256) bf16 g_gTl[2ll * 32 * 256 * 512];
__device__ __align__(256) bf16 g_ah[(size_t)MTOT * 512];
__device__ __align__(256) bf16 g_al[(size_t)MTOT * 512];
__device__ __align__(256) bf16 g_ensh[(size_t)MTOT * 512];
__device__ __align__(256) bf16 g_ensl[(size_t)MTOT * 512];
__device__ float g_xproj[2ll * MTOT * 768];
__device__ float g_out[2ll * MTOT * 256];
__device__ float g_attn[(size_t)MTOT * 512];
__device__ float g_colsum[BATCH * 256];

#define WOFF_W1 0
#define WOFF_W2 196608
#define WOFF_WC 393216
#define WOFF_WT 1161216
#define WOFF_WE 1929216

// ---------------- helpers ----------------
__device__ __forceinline__ unsigned long long dupf2(float x) {
    unsigned long long r; asm("mov.b64 %0, {%1, %1};" : "=l"(r) : "f"(x)); return r;
}
__device__ __forceinline__ float2 unpackf2(unsigned long long v) {
    float2 f; asm("mov.b64 {%0, %1}, %2;" : "=f"(f.x), "=f"(f.y) : "l"(v)); return f;
}
#define FMA2(d, a, b) asm("fma.rn.f32x2 %0, %1, %2, %0;" : "+l"(d) : "l"(a), "l"(b))

__device__ __forceinline__ unsigned smem_u32(const void* p) {
    unsigned r;
    asm("{ .reg .u64 t; cvta.to.shared.u64 t, %1; cvt.u32.u64 %0, t; }" : "=r"(r) : "l"(p));
    return r;
}
#define CLUSTER_SYNC_() do { \
    asm volatile("barrier.cluster.arrive.aligned;" ::: "memory"); \
    asm volatile("barrier.cluster.wait.aligned;"   ::: "memory"); } while (0)

#define LDSM4(r, addr) asm volatile( \
    "ldmatrix.sync.aligned.m8n8.x4.shared.b16 {%0,%1,%2,%3}, [%4];" \
    : "=r"((r)[0]), "=r"((r)[1]), "=r"((r)[2]), "=r"((r)[3]) : "r"(addr))

#define MMA_BF16(c, a, b0, b1) asm volatile( \
    "mma.sync.aligned.m16n8k16.row.col.f32.bf16.bf16.f32 " \
    "{%0,%1,%2,%3}, {%4,%5,%6,%7}, {%8,%9}, {%0,%1,%2,%3};" \
    : "+f"((c)[0]), "+f"((c)[1]), "+f"((c)[2]), "+f"((c)[3]) \
    : "r"((a)[0]), "r"((a)[1]), "r"((a)[2]), "r"((a)[3]), "r"(b0), "r"(b1))

__device__ __forceinline__ void cpa16(uint32_t dst, const void* src, unsigned bytes) {
    asm volatile("cp.async.cg.shared.global [%0], [%1], 16, %2;"
                 :: "r"(dst), "l"(src), "r"(bytes) : "memory");
}
#define CP_COMMIT() asm volatile("cp.async.commit_group;" ::: "memory")
#define CP_WAIT1()  asm volatile("cp.async.wait_group 1;" ::: "memory")

__device__ __forceinline__ void split2(float a, float b, bf162& h, bf162& l) {
    h = __floats2bfloat162_rn(a, b);
    float2 f = __bfloat1622float2(h);
    l = __floats2bfloat162_rn(a - f.x, b - f.y);
}

// ---------------- generic fp32 -> bf16 hi/lo split ----------------
__global__ void split4_kernel(const float4* __restrict__ s,
                              bf16* __restrict__ h, bf16* __restrict__ l, long n4) {
    long i = (long)blockIdx.x * 256 + threadIdx.x;
    if (i < n4) {
        float4 v = s[i];
        bf162 h01, l01, h23, l23;
        split2(v.x, v.y, h01, l01);
        split2(v.z, v.w, h23, l23);
        ((bf162*)h)[i * 2] = h01;     ((bf162*)h)[i * 2 + 1] = h23;
        ((bf162*)l)[i * 2] = l01;     ((bf162*)l)[i * 2 + 1] = l23;
    }
}

// ---------------- pack question tables transposed + split: qT[c][k] ----------------
__global__ void packqT_kernel(const float* __restrict__ qh, const float* __restrict__ qd,
                              bf16* __restrict__ th, bf16* __restrict__ tl) {
    __shared__ float t[32][33];
    int kb = blockIdx.x * 32, cb = blockIdx.y * 32;
    const float* src = (cb < 256) ? qh : qd;
    int cc0 = cb & 255;
    int x = threadIdx.x, y = threadIdx.y;
    for (int yy = y; yy < 32; yy += 8) {
        int k = kb + yy;
        t[yy][x] = (k < KX) ? src[(long)k * 256 + cc0 + x] : 0.f;
    }
    __syncthreads();
    if (kb + x < KX)
        for (int yy = y; yy < 32; yy += 8) {
            float v = t[x][yy];
            bf16 hv = __float2bfloat16(v);
            th[(long)(cb + yy) * KX + kb + x] = hv;
            tl[(long)(cb + yy) * KX + kb + x] = __float2bfloat16(v - __bfloat162float(hv));
        }
}

// ---------------- transpose + split GRU outputs: gT[(gb)*256+j][512] = gout[gb][t][j] ----------------
__global__ void transpSplit_kernel(const float* __restrict__ g,
                                   bf16* __restrict__ th, bf16* __restrict__ tl) {
    __shared__ float tile[32][33];
    int gb = blockIdx.z;
    int t0 = blockIdx.x * 32, j0 = blockIdx.y * 32;
    const float* src = g + (long)gb * SEQ * 256;
    int x = threadIdx.x, y = threadIdx.y;
    for (int yy = y; yy < 32; yy += 8) {
        int t = t0 + yy;
        tile[yy][x] = (t < SEQ) ? src[(long)t * 256 + j0 + x] : 0.f;
    }
    __syncthreads();
    for (int yy = y; yy < 32; yy += 8) {
        long o = (long)(gb * 256 + j0 + yy) * 512 + t0 + x;
        float v = tile[x][yy];
        bf16 hv = __float2bfloat16(v);
        th[o] = hv;
        tl[o] = __float2bfloat16(v - __bfloat162float(hv));
    }
}

// ---------------- pipelined bf16-split tensor-core NT GEMM ----------------
// C = (Ah+Al)@(Bh+Bl)^T dropping Al*Bl. 3-stage cp.async pipeline.
// OUT=0: fp32 C (+bias). OUT=1: split bf16 Ch/Cl. OUT=2: split of (colsum - acc).
#define PIPE 3
#define STG_B 40960           // bytes per stage: 4 arrays x 128 rows x 80B
#define MMA_SMEM (PIPE * STG_B)

template <int OUT>
__global__ __launch_bounds__(256, 1)
void mma_gemm(const bf16* __restrict__ Ah, const bf16* __restrict__ Al,
              const bf16* __restrict__ Bh, const bf16* __restrict__ Bl,
              float* __restrict__ C, bf16* __restrict__ Ch, bf16* __restrict__ Cl,
              const float* __restrict__ bias, const float* __restrict__ colsum,
              int M, int N, int K, int lda, int ldb, int ldc,
              long sA, long sB, long sC) {
    extern __shared__ __align__(16) bf16 smp[];
    const int z = blockIdx.z;
    Ah += (long)z * sA; Al += (long)z * sA;
    Bh += (long)z * sB; Bl += (long)z * sB;
    const long coff = (long)z * sC;
    const int row0 = blockIdx.y * 128, col0 = blockIdx.x * 128;
    const int tid = threadIdx.x, lane = tid & 31, wid = tid >> 5;
    const int wm0 = (wid & 3) * 32, wn0 = (wid >> 2) * 64;

    // loader mapping: row r = tid>>1, chunks c0,(c0+1) of 4 per row
    const int r = tid >> 1;
    const int c0 = (tid & 1) * 2;
    int arow = row0 + r; if (arow >= M) arow = M - 1;
    int brow = col0 + r; if (brow >= N) brow = N - 1;
    const char* pAh = (const char*)(Ah + (long)arow * lda);
    const char* pAl = (const char*)(Al + (long)arow * lda);
    const char* pBh = (const char*)(Bh + (long)brow * ldb);
    const char* pBl = (const char*)(Bl + (long)brow * ldb);
    const uint32_t dst0 = smem_u32(smp) + (uint32_t)(r * 80 + c0 * 16);
    const int NIT = (K + 31) >> 5;

    auto issue = [&](int it) {
        const uint32_t base = dst0 + (uint32_t)(it % PIPE) * STG_B;
        const int k0 = it << 5;
        #pragma unroll
        for (int cc = 0; cc < 2; ++cc) {
            int kh = k0 + (c0 + cc) * 8;
            int rem = K - kh;
            unsigned bytes = rem >= 8 ? 16u : (rem > 0 ? (unsigned)(rem * 2) : 0u);
            long go = (long)kh * 2;
            cpa16(base + cc * 16,         pAh + go, bytes);
            cpa16(base + 10240 + cc * 16, pAl + go, bytes);
            cpa16(base + 20480 + cc * 16, pBh + go, bytes);
            cpa16(base + 30720 + cc * 16, pBl + go, bytes);
        }
        CP_COMMIT();
    };

    float c[2][8][4];
    #pragma unroll
    for (int a = 0; a < 2; ++a)
        #pragma unroll
        for (int b = 0; b < 8; ++b)
            #pragma unroll
            for (int d = 0; d < 4; ++d) c[a][b][d] = 0.f;

    issue(0); issue(1);

    for (int it = 0; it < NIT; ++it) {
        CP_WAIT1();
        __syncthreads();
        if (it + PIPE - 1 < NIT) issue(it + PIPE - 1);
        else CP_COMMIT();                       // keep group accounting uniform

        const bf16* s0 = smp + (size_t)(it % PIPE) * (STG_B / 2);
        const bf16* s1 = s0 + 5120;
        const bf16* s2 = s0 + 10240;
        const bf16* s3 = s0 + 15360;

        #pragma unroll
        for (int kk = 0; kk < 2; ++kk) {
            uint32_t bh[4][4], bl[4][4];
            #pragma unroll
            for (int nt2 = 0; nt2 < 4; ++nt2) {
                int rb = wn0 + nt2 * 16 + (lane & 7) + ((lane >> 4) << 3);
                int cb2 = kk * 16 + (((lane >> 3) & 1) << 3);
                LDSM4(bh[nt2], smem_u32(s2 + rb * 40 + cb2));
                LDSM4(bl[nt2], smem_u32(s3 + rb * 40 + cb2));
            }
            #pragma unroll
            for (int mt = 0; mt < 2; ++mt) {
                int ra = wm0 + mt * 16 + (lane & 15);
                int ca = kk * 16 + ((lane >> 4) << 3);
                uint32_t ah[4], al[4];
                LDSM4(ah, smem_u32(s0 + ra * 40 + ca));
                LDSM4(al, smem_u32(s1 + ra * 40 + ca));
                #pragma unroll
                for (int nt2 = 0; nt2 < 4; ++nt2) {
                    #pragma unroll
                    for (int hh = 0; hh < 2; ++hh) {
                        float* cc = c[mt][nt2 * 2 + hh];
                        uint32_t b0h = bh[nt2][hh * 2], b1h = bh[nt2][hh * 2 + 1];
                        MMA_BF16(cc, ah, b0h, b1h);
                        MMA_BF16(cc, al, b0h, b1h);
                        MMA_BF16(cc, ah, bl[nt2][hh * 2], bl[nt2][hh * 2 + 1]);
                    }
                }
            }
        }
        __syncthreads();
    }

    // epilogue
    const int g = lane >> 2, tg = lane & 3;
    #pragma unroll
    for (int mt = 0; mt < 2; ++mt)
        #pragma unroll
        for (int nt = 0; nt < 8; ++nt) {
            int m0 = row0 + wm0 + mt * 16 + g;
            int n0 = col0 + wn0 + nt * 8 + tg * 2;
            if (n0 >= N) continue;
            float v0 = c[mt][nt][0], v1 = c[mt][nt][1];
            float v2 = c[mt][nt][2], v3 = c[mt][nt][3];
            if (OUT == 0) {
                float b0 = bias ? bias[n0] : 0.f;
                float b1 = bias ? bias[n0 + 1] : 0.f;
                if (m0 < M)
                    *(float2*)&C[coff + (long)m0 * ldc + n0] = make_float2(v0 + b0, v1 + b1);
                if (m0 + 8 < M)
                    *(float2*)&C[coff + (long)(m0 + 8) * ldc + n0] = make_float2(v2 + b0, v3 + b1);
            } else {
                if (OUT == 2) {
                    float cs0 = colsum[z * 256 + n0], cs1 = colsum[z * 256 + n0 + 1];
                    v0 = cs0 - v0; v1 = cs1 - v1; v2 = cs0 - v2; v3 = cs1 - v3;
                }
                bf162 h01, l01, h23, l23;
                split2(v0, v1, h01, l01);
                split2(v2, v3, h23, l23);
                if (m0 < M) {
                    *(bf162*)&Ch[coff + (long)m0 * ldc + n0] = h01;
                    *(bf162*)&Cl[coff + (long)m0 * ldc + n0] = l01;
                }
                if (m0 + 8 < M) {
                    *(bf162*)&Ch[coff + (long)(m0 + 8) * ldc + n0] = h23;
                    *(bf162*)&Cl[coff + (long)(m0 + 8) * ldc + n0] = l23;
                }
            }
        }
}

// ---------------- GRU recurrence: cluster-of-8 persistent scan ----------------
#define GRU_SMEM_FLOATS (96 * 260 + 96 + 2 * 1024 + 96 * 4)
#define GRU_SMEM_BYTES  (GRU_SMEM_FLOATS * 4)

__global__ void __cluster_dims__(8, 1, 1) __launch_bounds__(128, 1)
gru_kernel(const float* __restrict__ xproj,
           const float* __restrict__ whh1, const float* __restrict__ whh2,
           const float* __restrict__ bhh1, const float* __restrict__ bhh2,
           float* __restrict__ out) {
    extern __shared__ __align__(16) float sm[];
    float* Wm = sm;
    float* bias_s = sm + 96 * 260;
    float* h_s = bias_s + 96;
    float* gh_s = h_s + 2048;

    const int rank = blockIdx.x, bg = blockIdx.y, gru = blockIdx.z;
    const int tid = threadIdx.x;
    const float* whh = gru ? whh2 : whh1;
    const float* bhh = gru ? bhh2 : bhh1;

    for (int idx = tid; idx < 96 * 256; idx += 128) {
        int lr = idx >> 8, k = idx & 255;
        int grow = ((lr >> 5) << 8) + (rank << 5) + (lr & 31);
        Wm[lr * 260 + k] = whh[grow * 256 + k];
    }
    if (tid < 96)
        bias_s[tid] = bhh[((tid >> 5) << 8) + (rank << 5) + (tid & 31)];
    for (int i = tid; i < 2048; i += 128) h_s[i] = 0.f;
    __syncthreads();
    CLUSTER_SYNC_();

    const int b = tid >> 5, jj = tid & 31;
    const int jg = (rank << 5) + jj;
    const long mbase = (long)gru * MTOT + (long)bg * 4 * SEQ;
    const float* xp0 = xproj + mbase * 768;
    float* outp = out + mbase * 256;

    for (int t = 0; t < SEQ; ++t) {
        float* hc = h_s + ((t & 1) << 10);
        float* hn = h_s + (((t & 1) ^ 1) << 10);
        const float* xp = xp0 + ((long)b * SEQ + t) * 768;
        float xr = xp[jg], xz = xp[jg + 256], xn = xp[jg + 512];

        if (tid < 96) {
            const float* wrow = Wm + tid * 260;
            unsigned long long acc[4][2] = {};
            #pragma unroll 16
            for (int k = 0; k < 256; k += 4) {
                ulonglong2 w2 = *(const ulonglong2*)(wrow + k);
                #pragma unroll
                for (int bb = 0; bb < 4; ++bb) {
                    ulonglong2 h2 = *(const ulonglong2*)(hc + (bb << 8) + k);
                    FMA2(acc[bb][0], w2.x, h2.x);
                    FMA2(acc[bb][1], w2.y, h2.y);
                }
            }
            #pragma unroll
            for (int bb = 0; bb < 4; ++bb) {
                float2 p = unpackf2(acc[bb][0]);
                float2 q = unpackf2(acc[bb][1]);
                gh_s[tid * 4 + bb] = p.x + p.y + q.x + q.y + bias_s[tid];
            }
        }
        __syncthreads();
        {
            float ghr = gh_s[jj * 4 + b];
            float ghz = gh_s[(32 + jj) * 4 + b];
            float ghn = gh_s[(64 + jj) * 4 + b];
            float rr = 1.f / (1.f + __expf(-(xr + ghr)));
            float zz = 1.f / (1.f + __expf(-(xz + ghz)));
            float nn = tanhf(xn + rr * ghn);
            float hnew = (1.f - zz) * nn + zz * hc[(b << 8) + jg];
            outp[((long)b * SEQ + t) * 256 + jg] = hnew;
            unsigned laddr = smem_u32(hn + (b << 8) + jg);
            unsigned hbits = __float_as_uint(hnew);
            #pragma unroll
            for (int rd = 0; rd < 8; ++rd) {
                unsigned raddr;
                asm volatile("mapa.shared::cluster.u32 %0, %1, %2;" : "=r"(raddr) : "r"(laddr), "r"(rd));
                asm volatile("st.shared::cluster.b32 [%0], %1;" :: "r"(raddr), "r"(hbits) : "memory");
            }
        }
        CLUSTER_SYNC_();
    }
}

// ---------------- softmax rows of 500 -> split bf16 planes (zero pads 500..511) ----------------
__global__ void softmax_kernel(const float* __restrict__ scores,
                               bf16* __restrict__ ah, bf16* __restrict__ al) {
    __shared__ float red[8];
    const float* p = scores + (long)blockIdx.x * 512;
    int tid = threadIdx.x;
    float v1 = (tid < 500) ? p[tid] : -1e30f;
    float v2 = (tid + 256 < 500) ? p[tid + 256] : -1e30f;
    float m = fmaxf(v1, v2);
    #pragma unroll
    for (int o = 16; o; o >>= 1) m = fmaxf(m, __shfl_xor_sync(~0u, m, o));
    if ((tid & 31) == 0) red[tid >> 5] = m;
    __syncthreads();
    if (tid == 0) {
        float mm = red[0];
        #pragma unroll
        for (int i = 1; i < 8; ++i) mm = fmaxf(mm, red[i]);
        red[0] = mm;
    }
    __syncthreads();
    m = red[0];
    __syncthreads();
    float e1 = (tid < 500) ? __expf(v1 - m) : 0.f;
    float e2 = (tid + 256 < 500) ? __expf(v2 - m) : 0.f;
    float s = e1 + e2;
    #pragma unroll
    for (int o = 16; o; o >>= 1) s += __shfl_xor_sync(~0u, s, o);
    if ((tid & 31) == 0) red[tid >> 5] = s;
    __syncthreads();
    if (tid == 0) {
        float ss = 0.f;
        #pragma unroll
        for (int i = 0; i < 8; ++i) ss += red[i];
        red[0] = ss;
    }
    __syncthreads();
    float inv = 1.f / red[0];
    float a1 = e1 * inv, a2 = e2 * inv;
    long o1 = (long)blockIdx.x * 512 + tid;
    bf16 h1 = __float2bfloat16(a1);
    ah[o1] = h1;
    al[o1] = __float2bfloat16(a1 - __bfloat162float(h1));
    bf16 h2 = __float2bfloat16(a2);
    ah[o1 + 256] = h2;
    al[o1 + 256] = __float2bfloat16(a2 - __bfloat162float(h2));
}

__global__ void colsum_kernel(const float* __restrict__ outh, float* __restrict__ cs) {
    int b = blockIdx.x, j = threadIdx.x;
    const float* p = outh + (long)b * SEQ * 256 + j;
    float s = 0.f;
    for (int t = 0; t < SEQ; ++t) s += p[(long)t * 256];
    cs[b * 256 + j] = s;
}

// ---------------- host ----------------
static void launch_mm(int outk,
                      const bf16* Ah, const bf16* Al, const bf16* Bh, const bf16* Bl,
                      float* C, bf16* Ch, bf16* Cl, const float* bias, const float* colsum,
                      int M, int N, int K, int lda, int ldb, int ldc,
                      long sA, long sB, long sC, int batch) {
    dim3 grid((N + 127) / 128, (M + 127) / 128, batch);
    if (outk == 0)
        mma_gemm<0><<<grid, 256, MMA_SMEM>>>(Ah, Al, Bh, Bl, C, Ch, Cl, bias, colsum, M, N, K, lda, ldb, ldc, sA, sB, sC);
    else if (outk == 1)
        mma_gemm<1><<<grid, 256, MMA_SMEM>>>(Ah, Al, Bh, Bl, C, Ch, Cl, bias, colsum, M, N, K, lda, ldb, ldc, sA, sB, sC);
    else
        mma_gemm<2><<<grid, 256, MMA_SMEM>>>(Ah, Al, Bh, Bl, C, Ch, Cl, bias, colsum, M, N, K, lda, ldb, ldc, sA, sB, sC);
}
static void split_buf(const float* s, bf16* h, bf16* l, long n) {
    long n4 = n >> 2;
    split4_kernel<<<(unsigned)((n4 + 255) / 256), 256>>>((const float4*)s, h, l, n4);
}

extern "C" void kernel_launch(void* const* d_in, const int* in_sizes, int n_in,
                              void* d_out, int out_size) {
    const float* x     = (const float*)d_in[0];
    const float* qh    = (const float*)d_in[1];
    const float* qd    = (const float*)d_in[2];
    const float* g1wih = (const float*)d_in[3];
    const float* g1whh = (const float*)d_in[4];
    const float* g1bih = (const float*)d_in[5];
    const float* g1bhh = (const float*)d_in[6];
    const float* g2wih = (const float*)d_in[7];
    const float* g2whh = (const float*)d_in[8];
    const float* g2bih = (const float*)d_in[9];
    const float* g2bhh = (const float*)d_in[10];
    const float* fccw  = (const float*)d_in[11];
    const float* fccb  = (const float*)d_in[12];
    const float* fctw  = (const float*)d_in[13];
    const float* fctb  = (const float*)d_in[14];
    const float* fcew  = (const float*)d_in[15];
    const float* fceb  = (const float*)d_in[16];
    float* out = (float*)d_out;

    bf16 *xh, *xl, *qTh, *qTl, *wh, *wl, *xeh, *xel, *gh, *gl, *gTh, *gTl, *ah, *al, *ensh, *ensl;
    float *xproj, *gout, *attn, *colsum;
    cudaGetSymbolAddress((void**)&xh, g_xh);   cudaGetSymbolAddress((void**)&xl, g_xl);
    cudaGetSymbolAddress((void**)&qTh, g_qTh); cudaGetSymbolAddress((void**)&qTl, g_qTl);
    cudaGetSymbolAddress((void**)&wh, g_wh);   cudaGetSymbolAddress((void**)&wl, g_wl);
    cudaGetSymbolAddress((void**)&xeh, g_xeh); cudaGetSymbolAddress((void**)&xel, g_xel);
    cudaGetSymbolAddress((void**)&gh, g_gh);   cudaGetSymbolAddress((void**)&gl, g_gl);
    cudaGetSymbolAddress((void**)&gTh, g_gTh); cudaGetSymbolAddress((void**)&gTl, g_gTl);
    cudaGetSymbolAddress((void**)&ah, g_ah);   cudaGetSymbolAddress((void**)&al, g_al);
    cudaGetSymbolAddress((void**)&ensh, g_ensh); cudaGetSymbolAddress((void**)&ensl, g_ensl);
    cudaGetSymbolAddress((void**)&xproj, g_xproj);
    cudaGetSymbolAddress((void**)&gout, g_out);
    cudaGetSymbolAddress((void**)&attn, g_attn);
    cudaGetSymbolAddress((void**)&colsum, g_colsum);

    cudaFuncSetAttribute(mma_gemm<0>, cudaFuncAttributeMaxDynamicSharedMemorySize, MMA_SMEM);
    cudaFuncSetAttribute(mma_gemm<1>, cudaFuncAttributeMaxDynamicSharedMemorySize, MMA_SMEM);
    cudaFuncSetAttribute(mma_gemm<2>, cudaFuncAttributeMaxDynamicSharedMemorySize, MMA_SMEM);
    cudaFuncSetAttribute(gru_kernel, cudaFuncAttributeMaxDynamicSharedMemorySize, GRU_SMEM_BYTES);

    // 1. operand splits
    split_buf(x, xh, xl, (long)MTOT * KX);
    packqT_kernel<<<dim3((KX + 31) / 32, 16), dim3(32, 8)>>>(qh, qd, qTh, qTl);
    split_buf(g1wih, wh + WOFF_W1, wl + WOFF_W1, 768 * 256);
    split_buf(g2wih, wh + WOFF_W2, wl + WOFF_W2, 768 * 256);
    split_buf(fccw,  wh + WOFF_WC, wl + WOFF_WC, (long)NUM_Q * 256);
    split_buf(fctw,  wh + WOFF_WT, wl + WOFF_WT, (long)NUM_Q * 256);
    split_buf(fcew,  wh + WOFF_WE, wl + WOFF_WE, (long)NUM_Q * 512);

    // 2. embeddings -> xe split planes [16000][512]
    launch_mm(1, xh, xl, qTh, qTl, nullptr, xeh, xel, nullptr, nullptr,
              MTOT, 512, KX, KX, KX, 512, 0, 0, 0, 1);

    // 3. input projections [2][16000][768] fp32
    launch_mm(0, xeh, xel, wh + WOFF_W1, wl + WOFF_W1, xproj, nullptr, nullptr, g1bih, nullptr,
              MTOT, 768, 256, 512, 256, 768, 0, 0, 0, 1);
    launch_mm(0, xeh + 256, xel + 256, wh + WOFF_W2, wl + WOFF_W2, xproj + (long)MTOT * 768,
              nullptr, nullptr, g2bih, nullptr, MTOT, 768, 256, 512, 256, 768, 0, 0, 0, 1);

    // 4. GRU
    gru_kernel<<<dim3(8, 8, 2), 128, GRU_SMEM_BYTES>>>(xproj, g1whh, g2whh, g1bhh, g2bhh, gout);

    // 5. split + transpose-split hidden states
    split_buf(gout, gh, gl, 2L * MTOT * 256);
    transpSplit_kernel<<<dim3(16, 8, 64), dim3(32, 8)>>>(gout, gTh, gTl);

    const bf16 *ghh = gh, *ghl = gl;
    const bf16 *gdh = gh + (long)MTOT * 256, *gdl = gl + (long)MTOT * 256;

    // 6. per-branch logits
    launch_mm(0, ghh, ghl, wh + WOFF_WC, wl + WOFF_WC, out, nullptr, nullptr, fccb, nullptr,
              MTOT, NUM_Q, 256, 256, 256, NUM_Q, 0, 0, 0, 1);
    launch_mm(0, gdh, gdl, wh + WOFF_WT, wl + WOFF_WT, out + 48000000L, nullptr, nullptr, fctb, nullptr,
              MTOT, NUM_Q, 256, 256, 256, NUM_Q, 0, 0, 0, 1);

    // 7. colsum of out_h
    colsum_kernel<<<BATCH, 256>>>(gout, colsum);

    // 8. attention scores (batched) -> fp32 attn ld 512
    launch_mm(0, ghh, ghl, gdh, gdl, attn, nullptr, nullptr, nullptr, nullptr,
              SEQ, SEQ, 256, 256, 256, 512, 500L * 256, 500L * 256, 500L * 512, BATCH);

    // 9. softmax -> attn split planes (512 cols, zero-padded)
    softmax_kernel<<<MTOT, 256>>>(attn, ah, al);

    // 10. apply attention (batched MMA):
    //     ens[:, :256]  = attn @ out_d        (B = gT d-branch)
    //     ens[:, 256:]  = colsum - attn @ out_h
    launch_mm(1, ah, al, gTh + 4194304L, gTl + 4194304L, nullptr, ensh, ensl, nullptr, nullptr,
              SEQ, 256, 512, 512, 512, 512, 500L * 512, 131072L, 500L * 512, BATCH);
    launch_mm(2, ah, al, gTh, gTl, nullptr, ensh + 256, ensl + 256, nullptr, colsum,
              SEQ, 256, 512, 512, 512, 512, 500L * 512, 131072L, 500L * 512, BATCH);

    // 11. ensemble logits
    launch_mm(0, ensh, ensl, wh + WOFF_WE, wl + WOFF_WE, out + 96000000L, nullptr, nullptr, fceb, nullptr,
              MTOT, NUM_Q, 512, 512, 512, NUM_Q, 0, 0, 0, 1);
}

// round 6
// speedup vs baseline: 1.5260x; 1.1060x over previous
#include <cuda_runtime.h>
#include <cuda_bf16.h>
#include <cstdint>

#define NUM_Q 3000
#define BATCH 32
#define SEQ 500
#define MTOT (BATCH * SEQ)
#define KX (2 * NUM_Q)

typedef __nv_bfloat16 bf16;
typedef __nv_bfloat162 bf162;

// ---------------- scratch (bf16 hi/lo planes) ----------------
__device__ __align__(256) bf16 g_xh[(size_t)MTOT * KX + 64];
__device__ __align__(256) bf16 g_xl[(size_t)MTOT * KX + 64];
__device__ __align__(256) bf16 g_qTh[512 * KX + 64];
__device__ __align__(256) bf16 g_qTl[512 * KX + 64];
__device__ __align__(256) bf16 g_wh[3465216];
__device__ __align__(256) bf16 g_wl[3465216];
__device__ __align__(256) bf16 g_xeh[(size_t)MTOT * 512];
__device__ __align__(256) bf16 g_xel[(size_t)MTOT * 512];
__device__ __align__(256) bf16 g_gh[2ll * MTOT * 256];
__device__ __align__(256) bf16 g_gl[2ll * MTOT * 256];
__device__ __align__(256) bf16 g_gTh[2ll * 32 * 256 * 512];
__device__ __align__(256) bf16 g_gTl[2ll * 32 * 256 * 512];
__device__ __align__(256) bf16 g_ah[(size_t)MTOT * 512];
__device__ __align__(256) bf16 g_al[(size_t)MTOT * 512];
__device__ __align__(256) bf16 g_ensh[(size_t)MTOT * 512];
__device__ __align__(256) bf16 g_ensl[(size_t)MTOT * 512];
__device__ float g_xproj[2ll * MTOT * 768];
__device__ float g_out[2ll * MTOT * 256];
__device__ float g_attn[(size_t)MTOT * 512];
__device__ float g_colsum[BATCH * 256];

#define WOFF_W1 0
#define WOFF_W2 196608
#define WOFF_WC 393216
#define WOFF_WT 1161216
#define WOFF_WE 1929216

// ---------------- helpers ----------------
__device__ __forceinline__ unsigned long long dupf2(float x) {
    unsigned long long r; asm("mov.b64 %0, {%1, %1};" : "=l"(r) : "f"(x)); return r;
}
__device__ __forceinline__ float2 unpackf2(unsigned long long v) {
    float2 f; asm("mov.b64 {%0, %1}, %2;" : "=f"(f.x), "=f"(f.y) : "l"(v)); return f;
}
#define FMA2(d, a, b) asm("fma.rn.f32x2 %0, %1, %2, %0;" : "+l"(d) : "l"(a), "l"(b))

__device__ __forceinline__ unsigned smem_u32(const void* p) {
    unsigned r;
    asm("{ .reg .u64 t; cvta.to.shared.u64 t, %1; cvt.u32.u64 %0, t; }" : "=r"(r) : "l"(p));
    return r;
}
#define CLUSTER_SYNC_() do { \
    asm volatile("barrier.cluster.arrive.aligned;" ::: "memory"); \
    asm volatile("barrier.cluster.wait.aligned;"   ::: "memory"); } while (0)

#define LDSM4(r, addr) asm volatile( \
    "ldmatrix.sync.aligned.m8n8.x4.shared.b16 {%0,%1,%2,%3}, [%4];" \
    : "=r"((r)[0]), "=r"((r)[1]), "=r"((r)[2]), "=r"((r)[3]) : "r"(addr))

#define MMA_BF16(c, a, b0, b1) asm volatile( \
    "mma.sync.aligned.m16n8k16.row.col.f32.bf16.bf16.f32 " \
    "{%0,%1,%2,%3}, {%4,%5,%6,%7}, {%8,%9}, {%0,%1,%2,%3};" \
    : "+f"((c)[0]), "+f"((c)[1]), "+f"((c)[2]), "+f"((c)[3]) \
    : "r"((a)[0]), "r"((a)[1]), "r"((a)[2]), "r"((a)[3]), "r"(b0), "r"(b1))

__device__ __forceinline__ void cpa16(uint32_t dst, const void* src, unsigned bytes) {
    asm volatile("cp.async.cg.shared.global [%0], [%1], 16, %2;"
                 :: "r"(dst), "l"(src), "r"(bytes) : "memory");
}
#define CP_COMMIT() asm volatile("cp.async.commit_group;" ::: "memory")
#define CP_WAIT1()  asm volatile("cp.async.wait_group 1;" ::: "memory")

__device__ __forceinline__ void split2(float a, float b, bf162& h, bf162& l) {
    h = __floats2bfloat162_rn(a, b);
    float2 f = __bfloat1622float2(h);
    l = __floats2bfloat162_rn(a - f.x, b - f.y);
}

// ---------------- generic fp32 -> bf16 hi/lo split ----------------
__global__ void split4_kernel(const float4* __restrict__ s,
                              bf16* __restrict__ h, bf16* __restrict__ l, long n4) {
    long i = (long)blockIdx.x * 256 + threadIdx.x;
    if (i < n4) {
        float4 v = s[i];
        bf162 h01, l01, h23, l23;
        split2(v.x, v.y, h01, l01);
        split2(v.z, v.w, h23, l23);
        ((bf162*)h)[i * 2] = h01;     ((bf162*)h)[i * 2 + 1] = h23;
        ((bf162*)l)[i * 2] = l01;     ((bf162*)l)[i * 2 + 1] = l23;
    }
}

// ---------------- pack question tables transposed + split: qT[c][k] ----------------
__global__ void packqT_kernel(const float* __restrict__ qh, const float* __restrict__ qd,
                              bf16* __restrict__ th, bf16* __restrict__ tl) {
    __shared__ float t[32][33];
    int kb = blockIdx.x * 32, cb = blockIdx.y * 32;
    const float* src = (cb < 256) ? qh : qd;
    int cc0 = cb & 255;
    int x = threadIdx.x, y = threadIdx.y;
    for (int yy = y; yy < 32; yy += 8) {
        int k = kb + yy;
        t[yy][x] = (k < KX) ? src[(long)k * 256 + cc0 + x] : 0.f;
    }
    __syncthreads();
    if (kb + x < KX)
        for (int yy = y; yy < 32; yy += 8) {
            float v = t[x][yy];
            bf16 hv = __float2bfloat16(v);
            th[(long)(cb + yy) * KX + kb + x] = hv;
            tl[(long)(cb + yy) * KX + kb + x] = __float2bfloat16(v - __bfloat162float(hv));
        }
}

// ---------------- transpose + split GRU outputs ----------------
__global__ void transpSplit_kernel(const float* __restrict__ g,
                                   bf16* __restrict__ th, bf16* __restrict__ tl) {
    __shared__ float tile[32][33];
    int gb = blockIdx.z;
    int t0 = blockIdx.x * 32, j0 = blockIdx.y * 32;
    const float* src = g + (long)gb * SEQ * 256;
    int x = threadIdx.x, y = threadIdx.y;
    for (int yy = y; yy < 32; yy += 8) {
        int t = t0 + yy;
        tile[yy][x] = (t < SEQ) ? src[(long)t * 256 + j0 + x] : 0.f;
    }
    __syncthreads();
    for (int yy = y; yy < 32; yy += 8) {
        long o = (long)(gb * 256 + j0 + yy) * 512 + t0 + x;
        float v = tile[x][yy];
        bf16 hv = __float2bfloat16(v);
        th[o] = hv;
        tl[o] = __float2bfloat16(v - __bfloat162float(hv));
    }
}

// ---------------- pipelined bf16-split tensor-core NT GEMM ----------------
// C = (Ah+Al)@(Bh+Bl)^T dropping Al*Bl. 2-stage cp.async double buffer, 2 CTAs/SM.
#define PIPE 2
#define STG_B 40960
#define MMA_SMEM (PIPE * STG_B)

template <int OUT>
__global__ __launch_bounds__(256, 2)
void mma_gemm(const bf16* __restrict__ Ah, const bf16* __restrict__ Al,
              const bf16* __restrict__ Bh, const bf16* __restrict__ Bl,
              float* __restrict__ C, bf16* __restrict__ Ch, bf16* __restrict__ Cl,
              const float* __restrict__ bias, const float* __restrict__ colsum,
              int M, int N, int K, int lda, int ldb, int ldc,
              long sA, long sB, long sC) {
    extern __shared__ __align__(16) bf16 smp[];
    const int z = blockIdx.z;
    Ah += (long)z * sA; Al += (long)z * sA;
    Bh += (long)z * sB; Bl += (long)z * sB;
    const long coff = (long)z * sC;
    const int row0 = blockIdx.y * 128, col0 = blockIdx.x * 128;
    const int tid = threadIdx.x, lane = tid & 31, wid = tid >> 5;
    const int wm0 = (wid & 3) * 32, wn0 = (wid >> 2) * 64;

    const int r = tid >> 1;
    const int c0 = (tid & 1) * 2;
    int arow = row0 + r; if (arow >= M) arow = M - 1;
    int brow = col0 + r; if (brow >= N) brow = N - 1;
    const char* pAh = (const char*)(Ah + (long)arow * lda);
    const char* pAl = (const char*)(Al + (long)arow * lda);
    const char* pBh = (const char*)(Bh + (long)brow * ldb);
    const char* pBl = (const char*)(Bl + (long)brow * ldb);
    const uint32_t dst0 = smem_u32(smp) + (uint32_t)(r * 80 + c0 * 16);
    const int NIT = (K + 31) >> 5;

    auto issue = [&](int it) {
        const uint32_t base = dst0 + (uint32_t)(it & 1) * STG_B;
        const int k0 = it << 5;
        #pragma unroll
        for (int cc = 0; cc < 2; ++cc) {
            int kh = k0 + (c0 + cc) * 8;
            int rem = K - kh;
            unsigned bytes = rem >= 8 ? 16u : (rem > 0 ? (unsigned)(rem * 2) : 0u);
            long go = (long)kh * 2;
            cpa16(base + cc * 16,         pAh + go, bytes);
            cpa16(base + 10240 + cc * 16, pAl + go, bytes);
            cpa16(base + 20480 + cc * 16, pBh + go, bytes);
            cpa16(base + 30720 + cc * 16, pBl + go, bytes);
        }
        CP_COMMIT();
    };

    float c[2][8][4];
    #pragma unroll
    for (int a = 0; a < 2; ++a)
        #pragma unroll
        for (int b = 0; b < 8; ++b)
            #pragma unroll
            for (int d = 0; d < 4; ++d) c[a][b][d] = 0.f;

    issue(0); issue(1);

    for (int it = 0; it < NIT; ++it) {
        CP_WAIT1();
        __syncthreads();

        const bf16* s0 = smp + (size_t)(it & 1) * (STG_B / 2);
        const bf16* s1 = s0 + 5120;
        const bf16* s2 = s0 + 10240;
        const bf16* s3 = s0 + 15360;

        #pragma unroll
        for (int kk = 0; kk < 2; ++kk) {
            // A fragments for both m-tiles (16 regs live)
            uint32_t ah[2][4], al[2][4];
            #pragma unroll
            for (int mt = 0; mt < 2; ++mt) {
                int ra = wm0 + mt * 16 + (lane & 15);
                int ca = kk * 16 + ((lane >> 4) << 3);
                LDSM4(ah[mt], smem_u32(s0 + ra * 40 + ca));
                LDSM4(al[mt], smem_u32(s1 + ra * 40 + ca));
            }
            // stream B fragments (8 regs transient per nt2)
            #pragma unroll
            for (int nt2 = 0; nt2 < 4; ++nt2) {
                int rb = wn0 + nt2 * 16 + (lane & 7) + ((lane >> 4) << 3);
                int cb2 = kk * 16 + (((lane >> 3) & 1) << 3);
                uint32_t bh[4], bl[4];
                LDSM4(bh, smem_u32(s2 + rb * 40 + cb2));
                LDSM4(bl, smem_u32(s3 + rb * 40 + cb2));
                #pragma unroll
                for (int mt = 0; mt < 2; ++mt)
                    #pragma unroll
                    for (int hh = 0; hh < 2; ++hh) {
                        float* cc = c[mt][nt2 * 2 + hh];
                        MMA_BF16(cc, ah[mt], bh[hh * 2], bh[hh * 2 + 1]);
                        MMA_BF16(cc, al[mt], bh[hh * 2], bh[hh * 2 + 1]);
                        MMA_BF16(cc, ah[mt], bl[hh * 2], bl[hh * 2 + 1]);
                    }
            }
        }
        __syncthreads();
        if (it + 2 < NIT) issue(it + 2);
        else CP_COMMIT();
    }

    // epilogue
    const int g = lane >> 2, tg = lane & 3;
    #pragma unroll
    for (int mt = 0; mt < 2; ++mt)
        #pragma unroll
        for (int nt = 0; nt < 8; ++nt) {
            int m0 = row0 + wm0 + mt * 16 + g;
            int n0 = col0 + wn0 + nt * 8 + tg * 2;
            if (n0 >= N) continue;
            float v0 = c[mt][nt][0], v1 = c[mt][nt][1];
            float v2 = c[mt][nt][2], v3 = c[mt][nt][3];
            if (OUT == 0) {
                float b0 = bias ? bias[n0] : 0.f;
                float b1 = bias ? bias[n0 + 1] : 0.f;
                if (m0 < M)
                    *(float2*)&C[coff + (long)m0 * ldc + n0] = make_float2(v0 + b0, v1 + b1);
                if (m0 + 8 < M)
                    *(float2*)&C[coff + (long)(m0 + 8) * ldc + n0] = make_float2(v2 + b0, v3 + b1);
            } else {
                if (OUT == 2) {
                    float cs0 = colsum[z * 256 + n0], cs1 = colsum[z * 256 + n0 + 1];
                    v0 = cs0 - v0; v1 = cs1 - v1; v2 = cs0 - v2; v3 = cs1 - v3;
                }
                bf162 h01, l01, h23, l23;
                split2(v0, v1, h01, l01);
                split2(v2, v3, h23, l23);
                if (m0 < M) {
                    *(bf162*)&Ch[coff + (long)m0 * ldc + n0] = h01;
                    *(bf162*)&Cl[coff + (long)m0 * ldc + n0] = l01;
                }
                if (m0 + 8 < M) {
                    *(bf162*)&Ch[coff + (long)(m0 + 8) * ldc + n0] = h23;
                    *(bf162*)&Cl[coff + (long)(m0 + 8) * ldc + n0] = l23;
                }
            }
        }
}

// ---------------- GRU recurrence: cluster-of-8 persistent scan ----------------
#define GRU_SMEM_FLOATS (96 * 260 + 96 + 2 * 1024 + 96 * 4)
#define GRU_SMEM_BYTES  (GRU_SMEM_FLOATS * 4)

__global__ void __cluster_dims__(8, 1, 1) __launch_bounds__(128, 1)
gru_kernel(const float* __restrict__ xproj,
           const float* __restrict__ whh1, const float* __restrict__ whh2,
           const float* __restrict__ bhh1, const float* __restrict__ bhh2,
           float* __restrict__ out) {
    extern __shared__ __align__(16) float sm[];
    float* Wm = sm;
    float* bias_s = sm + 96 * 260;
    float* h_s = bias_s + 96;
    float* gh_s = h_s + 2048;

    const int rank = blockIdx.x, bg = blockIdx.y, gru = blockIdx.z;
    const int tid = threadIdx.x;
    const float* whh = gru ? whh2 : whh1;
    const float* bhh = gru ? bhh2 : bhh1;

    for (int idx = tid; idx < 96 * 256; idx += 128) {
        int lr = idx >> 8, k = idx & 255;
        int grow = ((lr >> 5) << 8) + (rank << 5) + (lr & 31);
        Wm[lr * 260 + k] = whh[grow * 256 + k];
    }
    if (tid < 96)
        bias_s[tid] = bhh[((tid >> 5) << 8) + (rank << 5) + (tid & 31)];
    for (int i = tid; i < 2048; i += 128) h_s[i] = 0.f;
    __syncthreads();
    CLUSTER_SYNC_();

    const int b = tid >> 5, jj = tid & 31;
    const int jg = (rank << 5) + jj;
    const long mbase = (long)gru * MTOT + (long)bg * 4 * SEQ;
    const float* xp0 = xproj + mbase * 768;
    float* outp = out + mbase * 256;

    for (int t = 0; t < SEQ; ++t) {
        float* hc = h_s + ((t & 1) << 10);
        float* hn = h_s + (((t & 1) ^ 1) << 10);
        const float* xp = xp0 + ((long)b * SEQ + t) * 768;
        float xr = xp[jg], xz = xp[jg + 256], xn = xp[jg + 512];

        if (tid < 96) {
            const float* wrow = Wm + tid * 260;
            unsigned long long acc[4][2] = {};
            #pragma unroll 16
            for (int k = 0; k < 256; k += 4) {
                ulonglong2 w2 = *(const ulonglong2*)(wrow + k);
                #pragma unroll
                for (int bb = 0; bb < 4; ++bb) {
                    ulonglong2 h2 = *(const ulonglong2*)(hc + (bb << 8) + k);
                    FMA2(acc[bb][0], w2.x, h2.x);
                    FMA2(acc[bb][1], w2.y, h2.y);
                }
            }
            #pragma unroll
            for (int bb = 0; bb < 4; ++bb) {
                float2 p = unpackf2(acc[bb][0]);
                float2 q = unpackf2(acc[bb][1]);
                gh_s[tid * 4 + bb] = p.x + p.y + q.x + q.y + bias_s[tid];
            }
        }
        __syncthreads();
        {
            float ghr = gh_s[jj * 4 + b];
            float ghz = gh_s[(32 + jj) * 4 + b];
            float ghn = gh_s[(64 + jj) * 4 + b];
            float rr = 1.f / (1.f + __expf(-(xr + ghr)));
            float zz = 1.f / (1.f + __expf(-(xz + ghz)));
            float nn = tanhf(xn + rr * ghn);
            float hnew = (1.f - zz) * nn + zz * hc[(b << 8) + jg];
            outp[((long)b * SEQ + t) * 256 + jg] = hnew;
            unsigned laddr = smem_u32(hn + (b << 8) + jg);
            unsigned hbits = __float_as_uint(hnew);
            #pragma unroll
            for (int rd = 0; rd < 8; ++rd) {
                unsigned raddr;
                asm volatile("mapa.shared::cluster.u32 %0, %1, %2;" : "=r"(raddr) : "r"(laddr), "r"(rd));
                asm volatile("st.shared::cluster.b32 [%0], %1;" :: "r"(raddr), "r"(hbits) : "memory");
            }
        }
        CLUSTER_SYNC_();
    }
}

// ---------------- softmax rows of 500 -> split bf16 planes ----------------
__global__ void softmax_kernel(const float* __restrict__ scores,
                               bf16* __restrict__ ah, bf16* __restrict__ al) {
    __shared__ float red[8];
    const float* p = scores + (long)blockIdx.x * 512;
    int tid = threadIdx.x;
    float v1 = (tid < 500) ? p[tid] : -1e30f;
    float v2 = (tid + 256 < 500) ? p[tid + 256] : -1e30f;
    float m = fmaxf(v1, v2);
    #pragma unroll
    for (int o = 16; o; o >>= 1) m = fmaxf(m, __shfl_xor_sync(~0u, m, o));
    if ((tid & 31) == 0) red[tid >> 5] = m;
    __syncthreads();
    if (tid == 0) {
        float mm = red[0];
        #pragma unroll
        for (int i = 1; i < 8; ++i) mm = fmaxf(mm, red[i]);
        red[0] = mm;
    }
    __syncthreads();
    m = red[0];
    __syncthreads();
    float e1 = (tid < 500) ? __expf(v1 - m) : 0.f;
    float e2 = (tid + 256 < 500) ? __expf(v2 - m) : 0.f;
    float s = e1 + e2;
    #pragma unroll
    for (int o = 16; o; o >>= 1) s += __shfl_xor_sync(~0u, s, o);
    if ((tid & 31) == 0) red[tid >> 5] = s;
    __syncthreads();
    if (tid == 0) {
        float ss = 0.f;
        #pragma unroll
        for (int i = 0; i < 8; ++i) ss += red[i];
        red[0] = ss;
    }
    __syncthreads();
    float inv = 1.f / red[0];
    float a1 = e1 * inv, a2 = e2 * inv;
    long o1 = (long)blockIdx.x * 512 + tid;
    bf16 h1 = __float2bfloat16(a1);
    ah[o1] = h1;
    al[o1] = __float2bfloat16(a1 - __bfloat162float(h1));
    bf16 h2 = __float2bfloat16(a2);
    ah[o1 + 256] = h2;
    al[o1 + 256] = __float2bfloat16(a2 - __bfloat162float(h2));
}

__global__ void colsum_kernel(const float* __restrict__ outh, float* __restrict__ cs) {
    int b = blockIdx.x, j = threadIdx.x;
    const float* p = outh + (long)b * SEQ * 256 + j;
    float s = 0.f;
    for (int t = 0; t < SEQ; ++t) s += p[(long)t * 256];
    cs[b * 256 + j] = s;
}

// ---------------- host ----------------
static void launch_mm(int outk,
                      const bf16* Ah, const bf16* Al, const bf16* Bh, const bf16* Bl,
                      float* C, bf16* Ch, bf16* Cl, const float* bias, const float* colsum,
                      int M, int N, int K, int lda, int ldb, int ldc,
                      long sA, long sB, long sC, int batch) {
    dim3 grid((N + 127) / 128, (M + 127) / 128, batch);
    if (outk == 0)
        mma_gemm<0><<<grid, 256, MMA_SMEM>>>(Ah, Al, Bh, Bl, C, Ch, Cl, bias, colsum, M, N, K, lda, ldb, ldc, sA, sB, sC);
    else if (outk == 1)
        mma_gemm<1><<<grid, 256, MMA_SMEM>>>(Ah, Al, Bh, Bl, C, Ch, Cl, bias, colsum, M, N, K, lda, ldb, ldc, sA, sB, sC);
    else
        mma_gemm<2><<<grid, 256, MMA_SMEM>>>(Ah, Al, Bh, Bl, C, Ch, Cl, bias, colsum, M, N, K, lda, ldb, ldc, sA, sB, sC);
}
static void split_buf(const float* s, bf16* h, bf16* l, long n) {
    long n4 = n >> 2;
    split4_kernel<<<(unsigned)((n4 + 255) / 256), 256>>>((const float4*)s, h, l, n4);
}

extern "C" void kernel_launch(void* const* d_in, const int* in_sizes, int n_in,
                              void* d_out, int out_size) {
    const float* x     = (const float*)d_in[0];
    const float* qh    = (const float*)d_in[1];
    const float* qd    = (const float*)d_in[2];
    const float* g1wih = (const float*)d_in[3];
    const float* g1whh = (const float*)d_in[4];
    const float* g1bih = (const float*)d_in[5];
    const float* g1bhh = (const float*)d_in[6];
    const float* g2wih = (const float*)d_in[7];
    const float* g2whh = (const float*)d_in[8];
    const float* g2bih = (const float*)d_in[9];
    const float* g2bhh = (const float*)d_in[10];
    const float* fccw  = (const float*)d_in[11];
    const float* fccb  = (const float*)d_in[12];
    const float* fctw  = (const float*)d_in[13];
    const float* fctb  = (const float*)d_in[14];
    const float* fcew  = (const float*)d_in[15];
    const float* fceb  = (const float*)d_in[16];
    float* out = (float*)d_out;

    bf16 *xh, *xl, *qTh, *qTl, *wh, *wl, *xeh, *xel, *gh, *gl, *gTh, *gTl, *ah, *al, *ensh, *ensl;
    float *xproj, *gout, *attn, *colsum;
    cudaGetSymbolAddress((void**)&xh, g_xh);   cudaGetSymbolAddress((void**)&xl, g_xl);
    cudaGetSymbolAddress((void**)&qTh, g_qTh); cudaGetSymbolAddress((void**)&qTl, g_qTl);
    cudaGetSymbolAddress((void**)&wh, g_wh);   cudaGetSymbolAddress((void**)&wl, g_wl);
    cudaGetSymbolAddress((void**)&xeh, g_xeh); cudaGetSymbolAddress((void**)&xel, g_xel);
    cudaGetSymbolAddress((void**)&gh, g_gh);   cudaGetSymbolAddress((void**)&gl, g_gl);
    cudaGetSymbolAddress((void**)&gTh, g_gTh); cudaGetSymbolAddress((void**)&gTl, g_gTl);
    cudaGetSymbolAddress((void**)&ah, g_ah);   cudaGetSymbolAddress((void**)&al, g_al);
    cudaGetSymbolAddress((void**)&ensh, g_ensh); cudaGetSymbolAddress((void**)&ensl, g_ensl);
    cudaGetSymbolAddress((void**)&xproj, g_xproj);
    cudaGetSymbolAddress((void**)&gout, g_out);
    cudaGetSymbolAddress((void**)&attn, g_attn);
    cudaGetSymbolAddress((void**)&colsum, g_colsum);

    cudaFuncSetAttribute(mma_gemm<0>, cudaFuncAttributeMaxDynamicSharedMemorySize, MMA_SMEM);
    cudaFuncSetAttribute(mma_gemm<1>, cudaFuncAttributeMaxDynamicSharedMemorySize, MMA_SMEM);
    cudaFuncSetAttribute(mma_gemm<2>, cudaFuncAttributeMaxDynamicSharedMemorySize, MMA_SMEM);
    cudaFuncSetAttribute(gru_kernel, cudaFuncAttributeMaxDynamicSharedMemorySize, GRU_SMEM_BYTES);

    // 1. operand splits
    split_buf(x, xh, xl, (long)MTOT * KX);
    packqT_kernel<<<dim3((KX + 31) / 32, 16), dim3(32, 8)>>>(qh, qd, qTh, qTl);
    split_buf(g1wih, wh + WOFF_W1, wl + WOFF_W1, 768 * 256);
    split_buf(g2wih, wh + WOFF_W2, wl + WOFF_W2, 768 * 256);
    split_buf(fccw,  wh + WOFF_WC, wl + WOFF_WC, (long)NUM_Q * 256);
    split_buf(fctw,  wh + WOFF_WT, wl + WOFF_WT, (long)NUM_Q * 256);
    split_buf(fcew,  wh + WOFF_WE, wl + WOFF_WE, (long)NUM_Q * 512);

    // 2. embeddings -> xe split planes [16000][512]
    launch_mm(1, xh, xl, qTh, qTl, nullptr, xeh, xel, nullptr, nullptr,
              MTOT, 512, KX, KX, KX, 512, 0, 0, 0, 1);

    // 3. input projections [2][16000][768] fp32
    launch_mm(0, xeh, xel, wh + WOFF_W1, wl + WOFF_W1, xproj, nullptr, nullptr, g1bih, nullptr,
              MTOT, 768, 256, 512, 256, 768, 0, 0, 0, 1);
    launch_mm(0, xeh + 256, xel + 256, wh + WOFF_W2, wl + WOFF_W2, xproj + (long)MTOT * 768,
              nullptr, nullptr, g2bih, nullptr, MTOT, 768, 256, 512, 256, 768, 0, 0, 0, 1);

    // 4. GRU
    gru_kernel<<<dim3(8, 8, 2), 128, GRU_SMEM_BYTES>>>(xproj, g1whh, g2whh, g1bhh, g2bhh, gout);

    // 5. split + transpose-split hidden states
    split_buf(gout, gh, gl, 2L * MTOT * 256);
    transpSplit_kernel<<<dim3(16, 8, 64), dim3(32, 8)>>>(gout, gTh, gTl);

    const bf16 *ghh = gh, *ghl = gl;
    const bf16 *gdh = gh + (long)MTOT * 256, *gdl = gl + (long)MTOT * 256;

    // 6. per-branch logits
    launch_mm(0, ghh, ghl, wh + WOFF_WC, wl + WOFF_WC, out, nullptr, nullptr, fccb, nullptr,
              MTOT, NUM_Q, 256, 256, 256, NUM_Q, 0, 0, 0, 1);
    launch_mm(0, gdh, gdl, wh + WOFF_WT, wl + WOFF_WT, out + 48000000L, nullptr, nullptr, fctb, nullptr,
              MTOT, NUM_Q, 256, 256, 256, NUM_Q, 0, 0, 0, 1);

    // 7. colsum of out_h
    colsum_kernel<<<BATCH, 256>>>(gout, colsum);

    // 8. attention scores (batched) -> fp32 attn ld 512
    launch_mm(0, ghh, ghl, gdh, gdl, attn, nullptr, nullptr, nullptr, nullptr,
              SEQ, SEQ, 256, 256, 256, 512, 500L * 256, 500L * 256, 500L * 512, BATCH);

    // 9. softmax -> attn split planes
    softmax_kernel<<<MTOT, 256>>>(attn, ah, al);

    // 10. apply attention (batched MMA)
    launch_mm(1, ah, al, gTh + 4194304L, gTl + 4194304L, nullptr, ensh, ensl, nullptr, nullptr,
              SEQ, 256, 512, 512, 512, 512, 500L * 512, 131072L, 500L * 512, BATCH);
    launch_mm(2, ah, al, gTh, gTl, nullptr, ensh + 256, ensl + 256, nullptr, colsum,
              SEQ, 256, 512, 512, 512, 512, 500L * 512, 131072L, 500L * 512, BATCH);

    // 11. ensemble logits
    launch_mm(0, ensh, ensl, wh + WOFF_WE, wl + WOFF_WE, out + 96000000L, nullptr, nullptr, fceb, nullptr,
              MTOT, NUM_Q, 512, 512, 512, NUM_Q, 0, 0, 0, 1);
}